// round 4
// baseline (speedup 1.0000x reference)
#include <cuda_runtime.h>
#include <cstdint>

#define S_LEN  4096
#define BATCH  2
#define NH     12
#define DH     64
#define DMODEL 768
#define MROWS  (BATCH * S_LEN)   // 8192

// Scratch (static device globals; allocation-free rule)
__device__ __align__(128) float g_q[BATCH * NH * S_LEN * DH];
__device__ __align__(128) float g_k[BATCH * NH * S_LEN * DH];
__device__ __align__(128) float g_v[BATCH * NH * S_LEN * DH];
__device__ __align__(128) float g_ctx[MROWS * DMODEL];

// ---------------------------------------------------------------------------
// tf32 helpers
// ---------------------------------------------------------------------------

__device__ __forceinline__ uint32_t tf32u(float x) {
    uint32_t r;
    asm("cvt.rna.tf32.f32 %0, %1;" : "=r"(r) : "f"(x));
    return r;
}

__device__ __forceinline__ void tf32split(float x, uint32_t& h, uint32_t& l) {
    h = tf32u(x);
    l = tf32u(x - __uint_as_float(h));
}

// D += A(16x8) * B(8x8), tf32, fp32 accum.
__device__ __forceinline__ void mma_tf32(float* c, const uint32_t* a, const uint32_t* b) {
    asm("mma.sync.aligned.m16n8k8.row.col.f32.tf32.tf32.f32 "
        "{%0,%1,%2,%3},{%4,%5,%6,%7},{%8,%9},{%0,%1,%2,%3};"
        : "+f"(c[0]), "+f"(c[1]), "+f"(c[2]), "+f"(c[3])
        : "r"(a[0]), "r"(a[1]), "r"(a[2]), "r"(a[3]), "r"(b[0]), "r"(b[1]));
}

// Fragment layouts (m16n8k8, lane = g*4+t, g=lane>>2, t=lane&3):
//  A (16x8 row-major): a0=(g,t) a1=(g+8,t) a2=(g,t+4) a3=(g+8,t+4)
//  B (8x8  col-major): b0=(k=t,n=g) b1=(k=t+4,n=g)
//  C: c0=(g,2t) c1=(g,2t+1) c2=(g+8,2t) c3=(g+8,2t+1)

// ---------------------------------------------------------------------------
// GEMM: tile 128x64, BK=16, 256 threads = 8 warps (warp_m 0..3, warp_n 0..1).
// Smem holds fragments pre-permuted; hi/lo tf32 split -> 3 mma passes.
// ---------------------------------------------------------------------------

// A fragment smem index for element (m in 0..127, kk in 0..15)
__device__ __forceinline__ int a_idx(int m, int kk) {
    int mtile = m >> 4, g = m & 7, rh = (m >> 3) & 1;
    int ksub = kk >> 3, kr = kk & 7, t = kr & 3, kh = kr >> 2;
    return ((mtile * 2 + ksub) << 7) + ((g * 4 + t) << 2) + kh * 2 + rh;
}
// B fragment smem index for element (kk in 0..15, n in 0..63)
__device__ __forceinline__ int b_idx(int kk, int n) {
    int ntile = n >> 3, g = n & 7;
    int ksub = kk >> 3, kr = kk & 7, t = kr & 3, kh = kr >> 2;
    return ((ntile * 2 + ksub) << 6) + ((g * 4 + t) << 1) + kh;
}

template <bool QKV>
__device__ __forceinline__ void gemm_body(
    const float* __restrict__ A, const float* __restrict__ B,
    float* __restrict__ out, const float* __restrict__ bo,
    int row0, int col0, float scale)
{
    __shared__ uint32_t Af[4096];   // hi [0,2048) lo [2048,4096)
    __shared__ uint32_t Bf[2048];   // hi [0,1024) lo [1024,2048)

    const int tid = threadIdx.x;
    const int lane = tid & 31, wid = tid >> 5;
    const int warp_m = wid >> 1, warp_n = wid & 1;
    const int g = lane >> 2, t = lane & 3;

    float c[2][4][4];
    #pragma unroll
    for (int mt = 0; mt < 2; mt++)
        #pragma unroll
        for (int nt = 0; nt < 4; nt++)
            #pragma unroll
            for (int i = 0; i < 4; i++) c[mt][nt][i] = 0.0f;

    const int am = tid >> 1, akq = (tid & 1) * 8;
    const int bkr = tid >> 4, bn4 = (tid & 15) * 4;

    for (int k0 = 0; k0 < DMODEL; k0 += 16) {
        // A tile load + split + fragment scatter
        {
            const float* ap = A + (size_t)(row0 + am) * DMODEL + k0 + akq;
            float4 v0 = *(const float4*)ap;
            float4 v1 = *(const float4*)(ap + 4);
            float va[8] = {v0.x, v0.y, v0.z, v0.w, v1.x, v1.y, v1.z, v1.w};
            #pragma unroll
            for (int j = 0; j < 8; j++) {
                int idx = a_idx(am, akq + j);
                tf32split(va[j], Af[idx], Af[2048 + idx]);
            }
        }
        // B tile load
        {
            float4 w4 = *(const float4*)(B + (size_t)(k0 + bkr) * DMODEL + col0 + bn4);
            float vb[4] = {w4.x, w4.y, w4.z, w4.w};
            #pragma unroll
            for (int j = 0; j < 4; j++) {
                int idx = b_idx(bkr, bn4 + j);
                tf32split(vb[j], Bf[idx], Bf[1024 + idx]);
            }
        }
        __syncthreads();

        #pragma unroll
        for (int ksub = 0; ksub < 2; ksub++) {
            uint4 ah[2], al[2];
            #pragma unroll
            for (int mt = 0; mt < 2; mt++) {
                int off = (((warp_m * 2 + mt) * 2 + ksub) << 7) + lane * 4;
                ah[mt] = *(const uint4*)&Af[off];
                al[mt] = *(const uint4*)&Af[2048 + off];
            }
            uint2 bh[4], bl[4];
            #pragma unroll
            for (int nt = 0; nt < 4; nt++) {
                int off = (((warp_n * 4 + nt) * 2 + ksub) << 6) + lane * 2;
                bh[nt] = *(const uint2*)&Bf[off];
                bl[nt] = *(const uint2*)&Bf[1024 + off];
            }
            #pragma unroll
            for (int mt = 0; mt < 2; mt++)
                #pragma unroll
                for (int nt = 0; nt < 4; nt++) {
                    mma_tf32(c[mt][nt], (const uint32_t*)&ah[mt], (const uint32_t*)&bh[nt]);
                    mma_tf32(c[mt][nt], (const uint32_t*)&ah[mt], (const uint32_t*)&bl[nt]);
                    mma_tf32(c[mt][nt], (const uint32_t*)&al[mt], (const uint32_t*)&bh[nt]);
                }
        }
        __syncthreads();
    }

    // Epilogue
    #pragma unroll
    for (int mt = 0; mt < 2; mt++) {
        int m0 = row0 + warp_m * 32 + mt * 16 + g;       // row for c0,c1
        int m1 = m0 + 8;                                  // row for c2,c3
        #pragma unroll
        for (int nt = 0; nt < 4; nt++) {
            int lcol = warp_n * 32 + nt * 8 + 2 * t;      // 0..63 (within N-tile)
            if (QKV) {
                // out is [B, H, S, 64]; head = col0/64, lcol = col within head
                int h = col0 >> 6;
                int b0 = m0 >> 12, s0 = m0 & 4095;
                int b1 = m1 >> 12, s1 = m1 & 4095;
                float2 o0 = make_float2(c[mt][nt][0] * scale, c[mt][nt][1] * scale);
                float2 o1 = make_float2(c[mt][nt][2] * scale, c[mt][nt][3] * scale);
                *(float2*)(out + (((size_t)(b0 * NH + h) * S_LEN + s0) << 6) + lcol) = o0;
                *(float2*)(out + (((size_t)(b1 * NH + h) * S_LEN + s1) << 6) + lcol) = o1;
            } else {
                int gcol = col0 + lcol;
                float bx = bo[gcol], by = bo[gcol + 1];
                float2 o0 = make_float2(c[mt][nt][0] + bx, c[mt][nt][1] + by);
                float2 o1 = make_float2(c[mt][nt][2] + bx, c[mt][nt][3] + by);
                *(float2*)(out + (size_t)m0 * DMODEL + gcol) = o0;
                *(float2*)(out + (size_t)m1 * DMODEL + gcol) = o1;
            }
        }
    }
}

__global__ __launch_bounds__(256) void qkv_gemm(
    const float* __restrict__ x, const float* __restrict__ Wq,
    const float* __restrict__ Wk, const float* __restrict__ Wv)
{
    const float* W;
    float* out;
    float scale;
    if (blockIdx.z == 0)      { W = Wq; out = g_q; scale = 0.125f; }  // 1/sqrt(64) into Q
    else if (blockIdx.z == 1) { W = Wk; out = g_k; scale = 1.0f; }
    else                      { W = Wv; out = g_v; scale = 1.0f; }
    gemm_body<true>(x, W, out, nullptr, blockIdx.y * 128, blockIdx.x * 64, scale);
}

__global__ __launch_bounds__(256) void out_gemm(
    const float* __restrict__ Wo, const float* __restrict__ bo,
    float* __restrict__ out)
{
    gemm_body<false>(g_ctx, Wo, out, bo, blockIdx.y * 128, blockIdx.x * 64, 1.0f);
}

// ---------------------------------------------------------------------------
// Flash attention (causal) on tensor cores.
// CTA: 128 q-rows, 8 warps (warp w owns rows w*16..w*16+15). 64 keys per kt.
// Q: split tf32 fragments in registers. K: split in smem. V: single tf32.
// P staged through the K buffer as A-fragments (single tf32).
// ---------------------------------------------------------------------------

__global__ __launch_bounds__(256) void flash_attn()
{
    __shared__ uint32_t Kf[8192];   // K hi [0,4096) lo [4096,8192); reused as Pf
    __shared__ uint32_t Vf[4096];

    const int tid = threadIdx.x;
    const int lane = tid & 31, wid = tid >> 5;
    const int g = lane >> 2, t = lane & 3;
    const int qb = blockIdx.x, bh = blockIdx.y;
    const int qrow0 = qb * 128 + wid * 16;

    const float* qp = g_q + (size_t)bh * S_LEN * DH;
    const float* kp = g_k + (size_t)bh * S_LEN * DH;
    const float* vp = g_v + (size_t)bh * S_LEN * DH;

    // Q fragments in registers (hi/lo split). Q pre-scaled by 1/8 in qkv_gemm.
    uint32_t qh[8][4], ql[8][4];
    {
        const float* r0 = qp + (size_t)(qrow0 + g) * DH;
        const float* r1 = qp + (size_t)(qrow0 + g + 8) * DH;
        #pragma unroll
        for (int ks = 0; ks < 8; ks++) {
            tf32split(r0[ks * 8 + t],     qh[ks][0], ql[ks][0]);
            tf32split(r1[ks * 8 + t],     qh[ks][1], ql[ks][1]);
            tf32split(r0[ks * 8 + t + 4], qh[ks][2], ql[ks][2]);
            tf32split(r1[ks * 8 + t + 4], qh[ks][3], ql[ks][3]);
        }
    }

    float o[8][4];
    #pragma unroll
    for (int nt = 0; nt < 8; nt++)
        #pragma unroll
        for (int i = 0; i < 4; i++) o[nt][i] = 0.0f;
    float m_a = -1e30f, m_b = -1e30f, l_a = 0.0f, l_b = 0.0f;

    const int kt_end = qb * 2 + 1;
    for (int kt = 0; kt <= kt_end; kt++) {
        __syncthreads();   // previous PV reads of Kf(P)/Vf complete

        // Load K (split) and V (single) into fragment-layout smem
        #pragma unroll
        for (int it = 0; it < 4; it++) {
            int idx = it * 256 + tid;
            int key = idx >> 4, d4 = (idx & 15) << 2;
            const float* kr = kp + (((size_t)kt * 64 + key) << 6) + d4;
            const float* vr = vp + (((size_t)kt * 64 + key) << 6) + d4;
            float4 kv = *(const float4*)kr;
            float4 vv = *(const float4*)vr;
            float ka[4] = {kv.x, kv.y, kv.z, kv.w};
            float va[4] = {vv.x, vv.y, vv.z, vv.w};
            #pragma unroll
            for (int j = 0; j < 4; j++) {
                int d = d4 + j;
                // K as B-frag for QK: (k-dim = d, n-dim = key)
                {
                    int ntile = key >> 3, gk = key & 7;
                    int ksub = d >> 3, dd = d & 7, tt = dd & 3, sl = dd >> 2;
                    int kidx = ((ntile * 8 + ksub) << 6) + ((gk * 4 + tt) << 1) + sl;
                    tf32split(ka[j], Kf[kidx], Kf[4096 + kidx]);
                }
                // V as B-frag for PV: (k-dim = key, n-dim = d)
                {
                    int ntv = d >> 3, gv = d & 7;
                    int ksv = key >> 3, kk = key & 7, tv = kk & 3, slv = kk >> 2;
                    int vidx = ((ntv * 8 + ksv) << 6) + ((gv * 4 + tv) << 1) + slv;
                    Vf[vidx] = tf32u(va[j]);
                }
            }
        }
        __syncthreads();

        // S = Q K^T (3-pass split)
        float s[8][4];
        #pragma unroll
        for (int nt = 0; nt < 8; nt++)
            #pragma unroll
            for (int i = 0; i < 4; i++) s[nt][i] = 0.0f;

        #pragma unroll
        for (int ks = 0; ks < 8; ks++) {
            #pragma unroll
            for (int nt = 0; nt < 8; nt++) {
                int off = ((nt * 8 + ks) << 6) + lane * 2;
                uint2 kh2 = *(const uint2*)&Kf[off];
                uint2 kl2 = *(const uint2*)&Kf[4096 + off];
                mma_tf32(s[nt], qh[ks], (const uint32_t*)&kh2);
                mma_tf32(s[nt], qh[ks], (const uint32_t*)&kl2);
                mma_tf32(s[nt], ql[ks], (const uint32_t*)&kh2);
            }
        }

        // Causal mask
        if (kt * 64 + 63 > qrow0) {
            int ra = qrow0 + g, rb = ra + 8;
            #pragma unroll
            for (int nt = 0; nt < 8; nt++) {
                int col = kt * 64 + nt * 8 + 2 * t;
                if (col > ra)     s[nt][0] = -1e30f;
                if (col + 1 > ra) s[nt][1] = -1e30f;
                if (col > rb)     s[nt][2] = -1e30f;
                if (col + 1 > rb) s[nt][3] = -1e30f;
            }
        }

        // Online softmax in registers (row groups = 4 lanes, shfl_xor 1,2)
        float mxa = -1e30f, mxb = -1e30f;
        #pragma unroll
        for (int nt = 0; nt < 8; nt++) {
            mxa = fmaxf(mxa, fmaxf(s[nt][0], s[nt][1]));
            mxb = fmaxf(mxb, fmaxf(s[nt][2], s[nt][3]));
        }
        mxa = fmaxf(mxa, __shfl_xor_sync(0xffffffffu, mxa, 1));
        mxa = fmaxf(mxa, __shfl_xor_sync(0xffffffffu, mxa, 2));
        mxb = fmaxf(mxb, __shfl_xor_sync(0xffffffffu, mxb, 1));
        mxb = fmaxf(mxb, __shfl_xor_sync(0xffffffffu, mxb, 2));

        float mna = fmaxf(m_a, mxa), mnb = fmaxf(m_b, mxb);
        float alpha_a = __expf(m_a - mna), alpha_b = __expf(m_b - mnb);
        m_a = mna; m_b = mnb;

        float sa = 0.0f, sb = 0.0f;
        #pragma unroll
        for (int nt = 0; nt < 8; nt++) {
            s[nt][0] = __expf(s[nt][0] - mna);
            s[nt][1] = __expf(s[nt][1] - mna);
            s[nt][2] = __expf(s[nt][2] - mnb);
            s[nt][3] = __expf(s[nt][3] - mnb);
            sa += s[nt][0] + s[nt][1];
            sb += s[nt][2] + s[nt][3];
        }
        sa += __shfl_xor_sync(0xffffffffu, sa, 1);
        sa += __shfl_xor_sync(0xffffffffu, sa, 2);
        sb += __shfl_xor_sync(0xffffffffu, sb, 1);
        sb += __shfl_xor_sync(0xffffffffu, sb, 2);
        l_a = l_a * alpha_a + sa;
        l_b = l_b * alpha_b + sb;

        #pragma unroll
        for (int nt = 0; nt < 8; nt++) {
            o[nt][0] *= alpha_a; o[nt][1] *= alpha_a;
            o[nt][2] *= alpha_b; o[nt][3] *= alpha_b;
        }

        __syncthreads();   // all QK reads of Kf done before P overwrite

        // Write P as A-fragments into Kf (per-warp region, single tf32)
        {
            int pbase = wid * 1024;
            #pragma unroll
            for (int nt = 0; nt < 8; nt++) {
                #pragma unroll
                for (int cc = 0; cc < 2; cc++) {
                    int kk = 2 * t + cc;
                    int ta = kk & 3, kh2 = kk >> 2;
                    int addr = pbase + (nt << 7) + ((g * 4 + ta) << 2) + kh2 * 2;
                    Kf[addr]     = tf32u(s[nt][cc]);       // row g
                    Kf[addr + 1] = tf32u(s[nt][2 + cc]);   // row g+8
                }
            }
        }
        __syncthreads();

        // O += P V (single tf32)
        #pragma unroll
        for (int ks = 0; ks < 8; ks++) {
            uint4 pa = *(const uint4*)&Kf[wid * 1024 + (ks << 7) + lane * 4];
            #pragma unroll
            for (int nt = 0; nt < 8; nt++) {
                uint2 vb = *(const uint2*)&Vf[((nt * 8 + ks) << 6) + lane * 2];
                mma_tf32(o[nt], (const uint32_t*)&pa, (const uint32_t*)&vb);
            }
        }
    }

    // Normalize and store ctx [B, S, 768]
    const int b = bh / NH, h = bh % NH;
    const float inva = 1.0f / l_a, invb = 1.0f / l_b;
    const int sa_ = qrow0 + g, sb_ = sa_ + 8;
    #pragma unroll
    for (int nt = 0; nt < 8; nt++) {
        int col = (h << 6) + nt * 8 + 2 * t;
        *(float2*)(g_ctx + ((size_t)(b * S_LEN) + sa_) * DMODEL + col) =
            make_float2(o[nt][0] * inva, o[nt][1] * inva);
        *(float2*)(g_ctx + ((size_t)(b * S_LEN) + sb_) * DMODEL + col) =
            make_float2(o[nt][2] * invb, o[nt][3] * invb);
    }
}

// ---------------------------------------------------------------------------

extern "C" void kernel_launch(void* const* d_in, const int* in_sizes, int n_in,
                              void* d_out, int out_size)
{
    const float* x  = (const float*)d_in[0];
    const float* Wq = (const float*)d_in[1];
    const float* Wk = (const float*)d_in[2];
    const float* Wv = (const float*)d_in[3];
    const float* Wo = (const float*)d_in[4];
    const float* bo = (const float*)d_in[5];
    float* out = (float*)d_out;

    qkv_gemm<<<dim3(DMODEL / 64, MROWS / 128, 3), 256>>>(x, Wq, Wk, Wv);
    flash_attn<<<dim3(S_LEN / 128, BATCH * NH), 256>>>();
    out_gemm<<<dim3(DMODEL / 64, MROWS / 128), 256>>>(Wo, bo, out);
}

// round 6
// speedup vs baseline: 1.9885x; 1.9885x over previous
#include <cuda_runtime.h>
#include <cstdint>

#define S_LEN  4096
#define BATCH  2
#define NH     12
#define DH     64
#define DMODEL 768
#define MROWS  (BATCH * S_LEN)   // 8192
#define BH     (BATCH * NH)      // 24

// ---------------------------------------------------------------------------
// Device scratch (allocation-free rule)
// ---------------------------------------------------------------------------
__device__ __align__(128) float g_q[BH * S_LEN * DH];
__device__ __align__(128) float g_k[BH * S_LEN * DH];
__device__ __align__(128) float g_v[BH * S_LEN * DH];
__device__ __align__(128) float g_ctx[MROWS * DMODEL];

#define APLANE 6291456u  // u32 per A-frag plane (both x/ctx [512mt*96kt*128] and q [6144mt*8kt*128])
__device__ __align__(128) uint32_t g_xf[2 * APLANE];   // x  A-frags hi/lo
__device__ __align__(128) uint32_t g_cf[2 * APLANE];   // ctx A-frags hi/lo
__device__ __align__(128) uint32_t g_qf[2 * APLANE];   // Q  A-frags hi/lo
__device__ __align__(128) uint32_t g_kf[12582912];     // K  B-frags, hi/lo packed uint4
__device__ __align__(128) uint32_t g_vf[6291456];      // V  B-frags, single tf32
#define WFRAG 1179648u
__device__ __align__(128) uint32_t g_wf[4 * WFRAG];    // Wq,Wk,Wv,Wo B-frags packed

// ---------------------------------------------------------------------------
// tf32 / mma helpers
// ---------------------------------------------------------------------------
__device__ __forceinline__ uint32_t tf32u(float x) {
    uint32_t r;
    asm("cvt.rna.tf32.f32 %0, %1;" : "=r"(r) : "f"(x));
    return r;
}
__device__ __forceinline__ void tf32split(float x, uint32_t& h, uint32_t& l) {
    h = tf32u(x);
    l = tf32u(x - __uint_as_float(h));
}
__device__ __forceinline__ void mma_tf32(float* c, const uint32_t* a, uint32_t b0, uint32_t b1) {
    asm("mma.sync.aligned.m16n8k8.row.col.f32.tf32.tf32.f32 "
        "{%0,%1,%2,%3},{%4,%5,%6,%7},{%8,%9},{%0,%1,%2,%3};"
        : "+f"(c[0]), "+f"(c[1]), "+f"(c[2]), "+f"(c[3])
        : "r"(a[0]), "r"(a[1]), "r"(a[2]), "r"(a[3]), "r"(b0), "r"(b1));
}
__device__ __forceinline__ void cpa16(uint32_t saddr, const void* g) {
    asm volatile("cp.async.cg.shared.global [%0], [%1], 16;" :: "r"(saddr), "l"(g) : "memory");
}

// ---------------------------------------------------------------------------
// Split kernels: build fragment-linear hi/lo tf32 layouts.
// A-frag (m16k8): [mt][kt][lane][4], reg = kh*2+rh; planes separated.
// B-frag (k8n8):  [nt][kt][lane][4] packed (hi0,hi1,lo0,lo1).
// ---------------------------------------------------------------------------

// src row-major [M][K]; one warp-lane per fragment lane.
__device__ __forceinline__ void split_a_body(
    const float* __restrict__ src, uint32_t* __restrict__ dst, int KT)
{
    int gtid = blockIdx.x * 256 + threadIdx.x;
    int lane = gtid & 31, gs = gtid >> 5;
    int g = lane >> 2, t = lane & 3;
    int kt = gs % KT, mt = gs / KT;
    int K = KT * 8;
    const float* p = src + (size_t)(mt * 16 + g) * K + kt * 8 + t;
    float v0 = p[0];
    float v1 = p[(size_t)8 * K];
    float v2 = p[4];
    float v3 = p[(size_t)8 * K + 4];
    uint4 h, l;
    tf32split(v0, h.x, l.x); tf32split(v1, h.y, l.y);
    tf32split(v2, h.z, l.z); tf32split(v3, h.w, l.w);
    uint32_t* o = dst + ((size_t)gs * 32 + lane) * 4;
    *(uint4*)o = h;
    *(uint4*)(o + APLANE) = l;
}

__global__ __launch_bounds__(256) void split_x_k(const float* __restrict__ x) {
    split_a_body(x, g_xf, 96);
}
__global__ __launch_bounds__(256) void split_ctx_k() {
    split_a_body(g_ctx, g_cf, 96);
}
__global__ __launch_bounds__(256) void split_q_k() {
    split_a_body(g_q, g_qf, 8);   // g_q viewed as [BH*S][64]
}

// weights: src [K=768][N=768] row-major
__global__ __launch_bounds__(256) void split_w_k(
    const float* __restrict__ w0, const float* __restrict__ w1,
    const float* __restrict__ w2, const float* __restrict__ w3)
{
    const float* src = (blockIdx.y == 0) ? w0 : (blockIdx.y == 1) ? w1
                     : (blockIdx.y == 2) ? w2 : w3;
    uint32_t* dst = g_wf + (size_t)blockIdx.y * WFRAG;
    int gtid = blockIdx.x * 256 + threadIdx.x;
    int lane = gtid & 31, gs = gtid >> 5;
    int g = lane >> 2, t = lane & 3;
    int kt = gs % 96, nt = gs / 96;
    int n = nt * 8 + g, k0 = kt * 8 + t;
    float v0 = src[(size_t)k0 * DMODEL + n];
    float v1 = src[(size_t)(k0 + 4) * DMODEL + n];
    uint4 u;
    tf32split(v0, u.x, u.z);
    tf32split(v1, u.y, u.w);
    *(uint4*)(dst + (size_t)gs * 128 + lane * 4) = u;
}

// K: B-frag over (k=d, n=key); src g_k [bh][key][64]
__global__ __launch_bounds__(256) void split_kb_k() {
    int gtid = blockIdx.x * 256 + threadIdx.x;
    int lane = gtid & 31, gs = gtid >> 5;
    int g = lane >> 2, t = lane & 3;
    int ktd = gs & 7;
    int ntg = gs >> 3;
    int bh = ntg >> 9, ntl = ntg & 511;
    int key = ntl * 8 + g, d0 = ktd * 8 + t;
    const float* p = g_k + (((size_t)bh * S_LEN + key) << 6);
    float v0 = p[d0], v1 = p[d0 + 4];
    uint4 u;
    tf32split(v0, u.x, u.z);
    tf32split(v1, u.y, u.w);
    *(uint4*)(g_kf + (size_t)gs * 128 + lane * 4) = u;
}

// V: B-frag over (k=key, n=d), single tf32, layout [ksg][ntd][lane][2]
__global__ __launch_bounds__(256) void split_vb_k() {
    int gtid = blockIdx.x * 256 + threadIdx.x;
    int lane = gtid & 31, gs = gtid >> 5;
    int g = lane >> 2, t = lane & 3;
    int ntd = gs & 7;
    int ksg = gs >> 3;
    int bh = ksg >> 9, ksl = ksg & 511;
    int key0 = ksl * 8 + t, d = ntd * 8 + g;
    const float* base = g_v + ((size_t)bh * S_LEN << 6);
    float v0 = base[((size_t)key0 << 6) + d];
    float v1 = base[((size_t)(key0 + 4) << 6) + d];
    uint2 u = make_uint2(tf32u(v0), tf32u(v1));
    *(uint2*)(g_vf + (size_t)gs * 64 + lane * 2) = u;
}

// ---------------------------------------------------------------------------
// GEMM core: 128x64 tile, BK=16, 256 thr (8 warps: wm=wid>>1 0..3, wn=wid&1),
// double-buffered smem fed by register prefetch; all LDG/STS/LDS vectorized.
// ---------------------------------------------------------------------------
struct GemmOut { float c[2][4][4]; };

__device__ __forceinline__ void gemm_core(
    const uint32_t* __restrict__ af,   // A frags hi plane (lo at +APLANE)
    const uint32_t* __restrict__ bf,   // B frags packed
    int mtBase, int ntBase, GemmOut& R)
{
    __shared__ uint32_t As[2][2][8][2][128];
    __shared__ uint32_t Bs[2][8][2][128];

    const int tid = threadIdx.x, lane = tid & 31, sub = tid >> 5;
    const int wm = sub >> 1, wn = sub & 1;

    #pragma unroll
    for (int mt = 0; mt < 2; mt++)
        #pragma unroll
        for (int nt = 0; nt < 4; nt++)
            #pragma unroll
            for (int i = 0; i < 4; i++) R.c[mt][nt][i] = 0.0f;

    uint4 pa[2][2], pb[2];
    #pragma unroll
    for (int ks = 0; ks < 2; ks++) {
        size_t ai = ((size_t)((mtBase + sub) * 96 + ks) * 32 + lane) * 4;
        pa[0][ks] = *(const uint4*)(af + ai);
        pa[1][ks] = *(const uint4*)(af + APLANE + ai);
        pb[ks] = *(const uint4*)(bf + ((size_t)((ntBase + sub) * 96 + ks) * 32 + lane) * 4);
    }
    #pragma unroll
    for (int ks = 0; ks < 2; ks++) {
        *(uint4*)&As[0][0][sub][ks][lane * 4] = pa[0][ks];
        *(uint4*)&As[0][1][sub][ks][lane * 4] = pa[1][ks];
        *(uint4*)&Bs[0][sub][ks][lane * 4]    = pb[ks];
    }
    __syncthreads();

    int buf = 0;
    for (int c2 = 1; c2 <= 48; c2++) {
        if (c2 < 48) {
            #pragma unroll
            for (int ks = 0; ks < 2; ks++) {
                size_t ai = ((size_t)((mtBase + sub) * 96 + c2 * 2 + ks) * 32 + lane) * 4;
                pa[0][ks] = *(const uint4*)(af + ai);
                pa[1][ks] = *(const uint4*)(af + APLANE + ai);
                pb[ks] = *(const uint4*)(bf + ((size_t)((ntBase + sub) * 96 + c2 * 2 + ks) * 32 + lane) * 4);
            }
        }
        #pragma unroll
        for (int ks = 0; ks < 2; ks++) {
            uint4 a0h = *(const uint4*)&As[buf][0][wm * 2 + 0][ks][lane * 4];
            uint4 a1h = *(const uint4*)&As[buf][0][wm * 2 + 1][ks][lane * 4];
            uint4 a0l = *(const uint4*)&As[buf][1][wm * 2 + 0][ks][lane * 4];
            uint4 a1l = *(const uint4*)&As[buf][1][wm * 2 + 1][ks][lane * 4];
            #pragma unroll
            for (int nt = 0; nt < 4; nt++) {
                uint4 b = *(const uint4*)&Bs[buf][wn * 4 + nt][ks][lane * 4];
                mma_tf32(R.c[0][nt], (const uint32_t*)&a0h, b.x, b.y);
                mma_tf32(R.c[0][nt], (const uint32_t*)&a0h, b.z, b.w);
                mma_tf32(R.c[0][nt], (const uint32_t*)&a0l, b.x, b.y);
                mma_tf32(R.c[1][nt], (const uint32_t*)&a1h, b.x, b.y);
                mma_tf32(R.c[1][nt], (const uint32_t*)&a1h, b.z, b.w);
                mma_tf32(R.c[1][nt], (const uint32_t*)&a1l, b.x, b.y);
            }
        }
        if (c2 < 48) {
            #pragma unroll
            for (int ks = 0; ks < 2; ks++) {
                *(uint4*)&As[buf ^ 1][0][sub][ks][lane * 4] = pa[0][ks];
                *(uint4*)&As[buf ^ 1][1][sub][ks][lane * 4] = pa[1][ks];
                *(uint4*)&Bs[buf ^ 1][sub][ks][lane * 4]    = pb[ks];
            }
            __syncthreads();
            buf ^= 1;
        }
    }
}

// QKV: grid (12 heads, 64 row-blocks, 3 tensors). Writes [bh][s][64] natural.
__global__ __launch_bounds__(256) void qkv_gemm() {
    const int z = blockIdx.z;
    float* out = (z == 0) ? g_q : (z == 1) ? g_k : g_v;
    const float scale = (z == 0) ? 0.125f : 1.0f;
    const uint32_t* bf = g_wf + (size_t)z * WFRAG;

    GemmOut R;
    gemm_core(g_xf, bf, blockIdx.y * 8, blockIdx.x * 8, R);

    const int lane = threadIdx.x & 31, wid = threadIdx.x >> 5;
    const int wm = wid >> 1, wn = wid & 1;
    const int g = lane >> 2, t = lane & 3;
    const int h = blockIdx.x;            // one head per 64-col block

    #pragma unroll
    for (int mt = 0; mt < 2; mt++) {
        int m0 = blockIdx.y * 128 + wm * 32 + mt * 16 + g;
        int m1 = m0 + 8;
        int b0 = m0 >> 12, s0 = m0 & 4095;
        int b1 = m1 >> 12, s1 = m1 & 4095;
        float* r0 = out + (((size_t)(b0 * NH + h) * S_LEN + s0) << 6);
        float* r1 = out + (((size_t)(b1 * NH + h) * S_LEN + s1) << 6);
        #pragma unroll
        for (int nt = 0; nt < 4; nt++) {
            int lcol = wn * 32 + nt * 8 + 2 * t;
            *(float2*)(r0 + lcol) = make_float2(R.c[mt][nt][0] * scale, R.c[mt][nt][1] * scale);
            *(float2*)(r1 + lcol) = make_float2(R.c[mt][nt][2] * scale, R.c[mt][nt][3] * scale);
        }
    }
}

__global__ __launch_bounds__(256) void out_gemm(
    const float* __restrict__ bo, float* __restrict__ out)
{
    GemmOut R;
    gemm_core(g_cf, g_wf + 3u * WFRAG, blockIdx.y * 8, blockIdx.x * 8, R);

    const int lane = threadIdx.x & 31, wid = threadIdx.x >> 5;
    const int wm = wid >> 1, wn = wid & 1;
    const int g = lane >> 2, t = lane & 3;
    const int col0 = blockIdx.x * 64;

    #pragma unroll
    for (int mt = 0; mt < 2; mt++) {
        int m0 = blockIdx.y * 128 + wm * 32 + mt * 16 + g;
        int m1 = m0 + 8;
        #pragma unroll
        for (int nt = 0; nt < 4; nt++) {
            int gcol = col0 + wn * 32 + nt * 8 + 2 * t;
            float bx = bo[gcol], by = bo[gcol + 1];
            *(float2*)(out + (size_t)m0 * DMODEL + gcol) =
                make_float2(R.c[mt][nt][0] + bx, R.c[mt][nt][1] + by);
            *(float2*)(out + (size_t)m1 * DMODEL + gcol) =
                make_float2(R.c[mt][nt][2] + bx, R.c[mt][nt][3] + by);
        }
    }
}

// ---------------------------------------------------------------------------
// Flash attention: 128 q-rows/CTA, 8 warps (16 rows each), 64-key tiles.
// K/V tiles cp.async double-buffered (96KB dyn smem). Q frags in registers.
// smem per buf (u32): K frags 8192 | V frags 4096; P overlays K region.
// ---------------------------------------------------------------------------
__global__ __launch_bounds__(256) void flash_attn()
{
    extern __shared__ uint32_t sm[];
    const uint32_t smBase = (uint32_t)__cvta_generic_to_shared(sm);

    const int tid = threadIdx.x, lane = tid & 31, wid = tid >> 5;
    const int g = lane >> 2, t = lane & 3;
    const int qb = (gridDim.x - 1) - blockIdx.x;   // big blocks first
    const int bh = blockIdx.y;
    const int qrow0 = qb * 128 + wid * 16;

    // Q fragments (hi/lo) resident in registers
    uint4 qh[8], ql[8];
    {
        const int mtg = bh * 256 + qb * 8 + wid;
        #pragma unroll
        for (int kt = 0; kt < 8; kt++) {
            size_t idx = ((size_t)(mtg * 8 + kt) * 32 + lane) * 4;
            qh[kt] = *(const uint4*)(g_qf + idx);
            ql[kt] = *(const uint4*)(g_qf + APLANE + idx);
        }
    }

    float o[8][4];
    #pragma unroll
    for (int nt = 0; nt < 8; nt++)
        #pragma unroll
        for (int i = 0; i < 4; i++) o[nt][i] = 0.0f;
    float m_a = -1e30f, m_b = -1e30f, l_a = 0.0f, l_b = 0.0f;

    const int kt_end = 2 * qb + 1;

    // prologue: tile 0 -> buf 0
    {
        size_t kb = (size_t)(bh * 512) * 1024;
        size_t vb = (size_t)(bh * 512) * 512;
        #pragma unroll
        for (int i = 0; i < 8; i++)
            cpa16(smBase + (i * 1024 + tid * 4) * 4, g_kf + kb + i * 1024 + tid * 4);
        #pragma unroll
        for (int i = 0; i < 4; i++)
            cpa16(smBase + (8192 + i * 1024 + tid * 4) * 4, g_vf + vb + i * 1024 + tid * 4);
        asm volatile("cp.async.commit_group;" ::: "memory");
    }

    for (int kt = 0; kt <= kt_end; kt++) {
        const int bufO = (kt & 1) * 12288;
        const bool hasNext = kt < kt_end;
        if (hasNext) {
            const int nb = (kt + 1) & 1;
            size_t kbase = (size_t)(bh * 512 + (kt + 1) * 8) * 1024;
            size_t vbase = (size_t)(bh * 512 + (kt + 1) * 8) * 512;
            #pragma unroll
            for (int i = 0; i < 8; i++)
                cpa16(smBase + (nb * 12288 + i * 1024 + tid * 4) * 4, g_kf + kbase + i * 1024 + tid * 4);
            #pragma unroll
            for (int i = 0; i < 4; i++)
                cpa16(smBase + (nb * 12288 + 8192 + i * 1024 + tid * 4) * 4, g_vf + vbase + i * 1024 + tid * 4);
            asm volatile("cp.async.commit_group;" ::: "memory");
            asm volatile("cp.async.wait_group 1;" ::: "memory");
        } else {
            asm volatile("cp.async.wait_group 0;" ::: "memory");
        }
        __syncthreads();

        const bool active = (kt * 64) <= (qrow0 + 15);
        float s[8][4];

        if (active) {
            #pragma unroll
            for (int nt = 0; nt < 8; nt++)
                #pragma unroll
                for (int i = 0; i < 4; i++) s[nt][i] = 0.0f;

            // S = Q K^T (3-pass split)
            #pragma unroll
            for (int ks = 0; ks < 8; ks++) {
                #pragma unroll
                for (int nt = 0; nt < 8; nt++) {
                    uint4 kb4 = *(const uint4*)&sm[bufO + ((nt * 8 + ks) * 32 + lane) * 4];
                    mma_tf32(s[nt], (const uint32_t*)&qh[ks], kb4.x, kb4.y);
                    mma_tf32(s[nt], (const uint32_t*)&qh[ks], kb4.z, kb4.w);
                    mma_tf32(s[nt], (const uint32_t*)&ql[ks], kb4.x, kb4.y);
                }
            }

            // causal mask
            if (kt * 64 + 63 > qrow0) {
                int ra = qrow0 + g, rb = ra + 8;
                #pragma unroll
                for (int nt = 0; nt < 8; nt++) {
                    int col = kt * 64 + nt * 8 + 2 * t;
                    if (col > ra)     s[nt][0] = -1e30f;
                    if (col + 1 > ra) s[nt][1] = -1e30f;
                    if (col > rb)     s[nt][2] = -1e30f;
                    if (col + 1 > rb) s[nt][3] = -1e30f;
                }
            }

            // online softmax (rows split across 4-lane groups)
            float mxa = -1e30f, mxb = -1e30f;
            #pragma unroll
            for (int nt = 0; nt < 8; nt++) {
                mxa = fmaxf(mxa, fmaxf(s[nt][0], s[nt][1]));
                mxb = fmaxf(mxb, fmaxf(s[nt][2], s[nt][3]));
            }
            mxa = fmaxf(mxa, __shfl_xor_sync(0xffffffffu, mxa, 1));
            mxa = fmaxf(mxa, __shfl_xor_sync(0xffffffffu, mxa, 2));
            mxb = fmaxf(mxb, __shfl_xor_sync(0xffffffffu, mxb, 1));
            mxb = fmaxf(mxb, __shfl_xor_sync(0xffffffffu, mxb, 2));

            float mna = fmaxf(m_a, mxa), mnb = fmaxf(m_b, mxb);
            float alpha_a = __expf(m_a - mna), alpha_b = __expf(m_b - mnb);
            m_a = mna; m_b = mnb;

            float sa = 0.0f, sb = 0.0f;
            #pragma unroll
            for (int nt = 0; nt < 8; nt++) {
                s[nt][0] = __expf(s[nt][0] - mna);
                s[nt][1] = __expf(s[nt][1] - mna);
                s[nt][2] = __expf(s[nt][2] - mnb);
                s[nt][3] = __expf(s[nt][3] - mnb);
                sa += s[nt][0] + s[nt][1];
                sb += s[nt][2] + s[nt][3];
            }
            sa += __shfl_xor_sync(0xffffffffu, sa, 1);
            sa += __shfl_xor_sync(0xffffffffu, sa, 2);
            sb += __shfl_xor_sync(0xffffffffu, sb, 1);
            sb += __shfl_xor_sync(0xffffffffu, sb, 2);
            l_a = l_a * alpha_a + sa;
            l_b = l_b * alpha_b + sb;

            #pragma unroll
            for (int nt = 0; nt < 8; nt++) {
                o[nt][0] *= alpha_a; o[nt][1] *= alpha_a;
                o[nt][2] *= alpha_b; o[nt][3] *= alpha_b;
            }
        }
        __syncthreads();   // all K reads done before P overlay

        if (active) {
            // P as A-fragments into this buf's K region (per-warp slice)
            #pragma unroll
            for (int nt = 0; nt < 8; nt++) {
                #pragma unroll
                for (int cc = 0; cc < 2; cc++) {
                    int kk = 2 * t + cc;
                    int addr = bufO + (wid * 8 + nt) * 128 + (g * 4 + (kk & 3)) * 4 + (kk >> 2) * 2;
                    *(uint2*)&sm[addr] = make_uint2(tf32u(s[nt][cc]), tf32u(s[nt][2 + cc]));
                }
            }
        }
        __syncthreads();

        if (active) {
            // O += P V (single tf32)
            #pragma unroll
            for (int ks = 0; ks < 8; ks++) {
                uint4 pa = *(const uint4*)&sm[bufO + (wid * 8 + ks) * 128 + lane * 4];
                #pragma unroll
                for (int nt = 0; nt < 8; nt++) {
                    uint2 vb2 = *(const uint2*)&sm[bufO + 8192 + ((ks * 8 + nt) * 32 + lane) * 2];
                    mma_tf32(o[nt], (const uint32_t*)&pa, vb2.x, vb2.y);
                }
            }
        }
        __syncthreads();   // PV reads done before next cp.async reuses this buf
    }

    // normalize + store ctx [B, S, 768]
    const int b = bh / NH, h = bh % NH;
    const float inva = 1.0f / l_a, invb = 1.0f / l_b;
    const int sa_ = qrow0 + g, sb_ = sa_ + 8;
    #pragma unroll
    for (int nt = 0; nt < 8; nt++) {
        int col = (h << 6) + nt * 8 + 2 * t;
        *(float2*)(g_ctx + ((size_t)(b * S_LEN) + sa_) * DMODEL + col) =
            make_float2(o[nt][0] * inva, o[nt][1] * inva);
        *(float2*)(g_ctx + ((size_t)(b * S_LEN) + sb_) * DMODEL + col) =
            make_float2(o[nt][2] * invb, o[nt][3] * invb);
    }
}

// ---------------------------------------------------------------------------

extern "C" void kernel_launch(void* const* d_in, const int* in_sizes, int n_in,
                              void* d_out, int out_size)
{
    const float* x  = (const float*)d_in[0];
    const float* Wq = (const float*)d_in[1];
    const float* Wk = (const float*)d_in[2];
    const float* Wv = (const float*)d_in[3];
    const float* Wo = (const float*)d_in[4];
    const float* bo = (const float*)d_in[5];
    float* out = (float*)d_out;

    cudaFuncSetAttribute(flash_attn, cudaFuncAttributeMaxDynamicSharedMemorySize, 98304);

    split_w_k<<<dim3(1152, 4), 256>>>(Wq, Wk, Wv, Wo);
    split_x_k<<<6144, 256>>>(x);
    qkv_gemm<<<dim3(12, 64, 3), 256>>>();
    split_q_k<<<6144, 256>>>();
    split_kb_k<<<12288, 256>>>();
    split_vb_k<<<12288, 256>>>();
    flash_attn<<<dim3(32, BH), 256, 98304>>>();
    split_ctx_k<<<6144, 256>>>();
    out_gemm<<<dim3(12, 64), 256>>>(bo, out);
}

// round 7
// speedup vs baseline: 3.1836x; 1.6010x over previous
#include <cuda_runtime.h>
#include <cuda_bf16.h>
#include <cstdint>

#define S_LEN  4096
#define BATCH  2
#define NH     12
#define DH     64
#define DMODEL 768
#define MROWS  (BATCH * S_LEN)   // 8192
#define BH     (BATCH * NH)      // 24
#define AP2    3145728u          // u32 per A-frag plane (512mt*48kt2*128 == 6144mt*4kt2*128)

// ---------------------------------------------------------------------------
// Device scratch (allocation-free rule)
// ---------------------------------------------------------------------------
__device__ __align__(128) float    g_v [BH * S_LEN * DH];      // V natural (for split_vb)
__device__ __align__(128) uint32_t g_xf[2 * AP2];              // x   A-frags hi/lo (bf16x2)
__device__ __align__(128) uint32_t g_cf[2 * AP2];              // ctx A-frags hi/lo
__device__ __align__(128) uint32_t g_qf[2 * AP2];              // Q   A-frags hi/lo
__device__ __align__(128) uint32_t g_kf[6291456];              // K B-frags packed (bh0,bh1,bl0,bl1)
__device__ __align__(128) uint32_t g_vf[6291456];              // V B-frags packed
#define WFRAG 589824u
__device__ __align__(128) uint32_t g_wf[4 * WFRAG];            // Wq,Wk,Wv,Wo B-frags packed

// ---------------------------------------------------------------------------
// bf16 / mma helpers
// ---------------------------------------------------------------------------
__device__ __forceinline__ float bfhi(float x) {
    return __bfloat162float(__float2bfloat16(x));
}
// pack (k-even, k-odd) into one b32 (even in low half)
__device__ __forceinline__ uint32_t packbf(float e0, float e1) {
    uint32_t r;
    asm("cvt.rn.bf16x2.f32 %0, %1, %2;" : "=r"(r) : "f"(e1), "f"(e0));
    return r;
}
__device__ __forceinline__ void mma_bf16(float* c, const uint32_t* a, uint32_t b0, uint32_t b1) {
    asm("mma.sync.aligned.m16n8k16.row.col.f32.bf16.bf16.f32 "
        "{%0,%1,%2,%3},{%4,%5,%6,%7},{%8,%9},{%0,%1,%2,%3};"
        : "+f"(c[0]), "+f"(c[1]), "+f"(c[2]), "+f"(c[3])
        : "r"(a[0]), "r"(a[1]), "r"(a[2]), "r"(a[3]), "r"(b0), "r"(b1));
}
__device__ __forceinline__ void cpa16(uint32_t saddr, const void* g) {
    asm volatile("cp.async.cg.shared.global [%0], [%1], 16;" :: "r"(saddr), "l"(g) : "memory");
}
// split two elements into hi-pack and lo-pack
__device__ __forceinline__ void sp2(float e0, float e1, uint32_t& h, uint32_t& l) {
    float h0 = bfhi(e0), h1 = bfhi(e1);
    h = packbf(h0, h1);
    l = packbf(e0 - h0, e1 - h1);
}

// Fragment layouts (m16n8k16, lane = g*4+t):
//  A: a0=(g,2t..2t+1) a1=(g+8,2t..) a2=(g,2t+8..) a3=(g+8,2t+8..)
//  B: b0=(k 2t..2t+1, n g)  b1=(k 2t+8..2t+9, n g)
//  C: c0=(g,2t) c1=(g,2t+1) c2=(g+8,2t) c3=(g+8,2t+1)

// ---------------------------------------------------------------------------
// Split kernels (run once per call; cheap, bandwidth-bound)
// ---------------------------------------------------------------------------

// x -> A-frags: gs = mt*48 + kt2
__global__ __launch_bounds__(256) void split_x_k(const float* __restrict__ x) {
    int gtid = blockIdx.x * 256 + threadIdx.x;
    int lane = gtid & 31, gs = gtid >> 5;
    int g = lane >> 2, t = lane & 3;
    int mt = gs / 48, kt2 = gs % 48;
    const float* p = x + (size_t)(mt * 16 + g) * DMODEL + kt2 * 16 + 2 * t;
    float2 v00 = *(const float2*)p;
    float2 v10 = *(const float2*)(p + 8 * DMODEL);
    float2 v01 = *(const float2*)(p + 8);
    float2 v11 = *(const float2*)(p + 8 * DMODEL + 8);
    uint4 h, l;
    sp2(v00.x, v00.y, h.x, l.x);
    sp2(v10.x, v10.y, h.y, l.y);
    sp2(v01.x, v01.y, h.z, l.z);
    sp2(v11.x, v11.y, h.w, l.w);
    uint32_t* o = g_xf + (size_t)gs * 128 + lane * 4;
    *(uint4*)o = h;
    *(uint4*)(o + AP2) = l;
}

// weights [K=768][N=768] -> B-frags packed: gs = nt*48 + kt2
__global__ __launch_bounds__(256) void split_w_k(
    const float* __restrict__ w0, const float* __restrict__ w1,
    const float* __restrict__ w2, const float* __restrict__ w3)
{
    const float* src = (blockIdx.y == 0) ? w0 : (blockIdx.y == 1) ? w1
                     : (blockIdx.y == 2) ? w2 : w3;
    uint32_t* dst = g_wf + (size_t)blockIdx.y * WFRAG;
    int gtid = blockIdx.x * 256 + threadIdx.x;
    int lane = gtid & 31, gs = gtid >> 5;
    int g = lane >> 2, t = lane & 3;
    int nt = gs / 48, kt2 = gs % 48;
    int n = nt * 8 + g, k0 = kt2 * 16 + 2 * t;
    float v0 = src[(size_t)k0 * DMODEL + n];
    float v1 = src[(size_t)(k0 + 1) * DMODEL + n];
    float v2 = src[(size_t)(k0 + 8) * DMODEL + n];
    float v3 = src[(size_t)(k0 + 9) * DMODEL + n];
    uint4 u;
    sp2(v0, v1, u.x, u.z);
    sp2(v2, v3, u.y, u.w);
    *(uint4*)(dst + (size_t)gs * 128 + lane * 4) = u;
}

// V natural -> B-frags (k=key, n=d) packed: gs = (bh*256+ks2)*8 + ntd
__global__ __launch_bounds__(256) void split_vb_k() {
    int gtid = blockIdx.x * 256 + threadIdx.x;
    int lane = gtid & 31, gs = gtid >> 5;
    int g = lane >> 2, t = lane & 3;
    int ntd = gs & 7;
    int r = gs >> 3;
    int ks2 = r & 255, bh = r >> 8;
    int k0 = ks2 * 16 + 2 * t, d = ntd * 8 + g;
    const float* base = g_v + ((size_t)bh * S_LEN << 6);
    float v0 = base[((size_t)k0 << 6) + d];
    float v1 = base[((size_t)(k0 + 1) << 6) + d];
    float v2 = base[((size_t)(k0 + 8) << 6) + d];
    float v3 = base[((size_t)(k0 + 9) << 6) + d];
    uint4 u;
    sp2(v0, v1, u.x, u.z);
    sp2(v2, v3, u.y, u.w);
    *(uint4*)(g_vf + (size_t)gs * 128 + lane * 4) = u;
}

// ---------------------------------------------------------------------------
// GEMM core: 128x64 tile, BK=32 (2 k16 chunks/stage), 256 thr, double-buffered.
// ---------------------------------------------------------------------------
struct GemmOut { float c[2][4][4]; };

__device__ __forceinline__ void gemm_core(
    const uint32_t* __restrict__ af,   // A frags hi plane (lo at +AP2)
    const uint32_t* __restrict__ bf,   // B frags packed
    int mtBase, int ntBase, GemmOut& R)
{
    __shared__ uint32_t As[2][2][8][2][128];
    __shared__ uint32_t Bs[2][8][2][128];

    const int tid = threadIdx.x, lane = tid & 31, sub = tid >> 5;
    const int wm = sub >> 1, wn = sub & 1;

    #pragma unroll
    for (int mt = 0; mt < 2; mt++)
        #pragma unroll
        for (int nt = 0; nt < 4; nt++)
            #pragma unroll
            for (int i = 0; i < 4; i++) R.c[mt][nt][i] = 0.0f;

    uint4 pa[2][2], pb[2];
    #pragma unroll
    for (int ks = 0; ks < 2; ks++) {
        size_t ai = ((size_t)((mtBase + sub) * 48 + ks) * 32 + lane) * 4;
        pa[0][ks] = *(const uint4*)(af + ai);
        pa[1][ks] = *(const uint4*)(af + AP2 + ai);
        pb[ks] = *(const uint4*)(bf + ((size_t)((ntBase + sub) * 48 + ks) * 32 + lane) * 4);
    }
    #pragma unroll
    for (int ks = 0; ks < 2; ks++) {
        *(uint4*)&As[0][0][sub][ks][lane * 4] = pa[0][ks];
        *(uint4*)&As[0][1][sub][ks][lane * 4] = pa[1][ks];
        *(uint4*)&Bs[0][sub][ks][lane * 4]    = pb[ks];
    }
    __syncthreads();

    int buf = 0;
    for (int st = 1; st <= 24; st++) {
        if (st < 24) {
            #pragma unroll
            for (int ks = 0; ks < 2; ks++) {
                size_t ai = ((size_t)((mtBase + sub) * 48 + st * 2 + ks) * 32 + lane) * 4;
                pa[0][ks] = *(const uint4*)(af + ai);
                pa[1][ks] = *(const uint4*)(af + AP2 + ai);
                pb[ks] = *(const uint4*)(bf + ((size_t)((ntBase + sub) * 48 + st * 2 + ks) * 32 + lane) * 4);
            }
        }
        #pragma unroll
        for (int ks = 0; ks < 2; ks++) {
            uint4 a0h = *(const uint4*)&As[buf][0][wm * 2 + 0][ks][lane * 4];
            uint4 a1h = *(const uint4*)&As[buf][0][wm * 2 + 1][ks][lane * 4];
            uint4 a0l = *(const uint4*)&As[buf][1][wm * 2 + 0][ks][lane * 4];
            uint4 a1l = *(const uint4*)&As[buf][1][wm * 2 + 1][ks][lane * 4];
            #pragma unroll
            for (int nt = 0; nt < 4; nt++) {
                uint4 b = *(const uint4*)&Bs[buf][wn * 4 + nt][ks][lane * 4];
                mma_bf16(R.c[0][nt], (const uint32_t*)&a0h, b.x, b.y);
                mma_bf16(R.c[0][nt], (const uint32_t*)&a0h, b.z, b.w);
                mma_bf16(R.c[0][nt], (const uint32_t*)&a0l, b.x, b.y);
                mma_bf16(R.c[1][nt], (const uint32_t*)&a1h, b.x, b.y);
                mma_bf16(R.c[1][nt], (const uint32_t*)&a1h, b.z, b.w);
                mma_bf16(R.c[1][nt], (const uint32_t*)&a1l, b.x, b.y);
            }
        }
        if (st < 24) {
            #pragma unroll
            for (int ks = 0; ks < 2; ks++) {
                *(uint4*)&As[buf ^ 1][0][sub][ks][lane * 4] = pa[0][ks];
                *(uint4*)&As[buf ^ 1][1][sub][ks][lane * 4] = pa[1][ks];
                *(uint4*)&Bs[buf ^ 1][sub][ks][lane * 4]    = pb[ks];
            }
            __syncthreads();
            buf ^= 1;
        }
    }
}

// QKV GEMM. z=0: Q -> A-frags (scaled). z=1: K -> B-frags. z=2: V natural.
__global__ __launch_bounds__(256) void qkv_gemm() {
    const int z = blockIdx.z;
    const uint32_t* bfw = g_wf + (size_t)z * WFRAG;

    GemmOut R;
    gemm_core(g_xf, bfw, blockIdx.y * 8, blockIdx.x * 8, R);

    const int lane = threadIdx.x & 31, wid = threadIdx.x >> 5;
    const int wm = wid >> 1, wn = wid & 1;
    const int g = lane >> 2, t = lane & 3;
    const int h = blockIdx.x;            // one head per 64-col block

    #pragma unroll
    for (int mt = 0; mt < 2; mt++) {
        int m0 = blockIdx.y * 128 + wm * 32 + mt * 16;    // row-tile base (mult of 16)
        int b = m0 >> 12, s0 = m0 & 4095;
        int bh = b * NH + h;

        if (z == 0) {
            // Q A-frags, scale 1/8
            int mq = bh * 256 + (s0 >> 4);
            #pragma unroll
            for (int j = 0; j < 2; j++) {
                int ne = 2 * j, no = ne + 1;
                uint4 hq, lq;
                sp2(R.c[mt][ne][0] * 0.125f, R.c[mt][ne][1] * 0.125f, hq.x, lq.x);
                sp2(R.c[mt][ne][2] * 0.125f, R.c[mt][ne][3] * 0.125f, hq.y, lq.y);
                sp2(R.c[mt][no][0] * 0.125f, R.c[mt][no][1] * 0.125f, hq.z, lq.z);
                sp2(R.c[mt][no][2] * 0.125f, R.c[mt][no][3] * 0.125f, hq.w, lq.w);
                uint32_t* o = g_qf + ((size_t)(mq * 4 + wn * 2 + j) * 32 + lane) * 4;
                *(uint4*)o = hq;
                *(uint4*)(o + AP2) = lq;
            }
        } else if (z == 1) {
            // K B-frags: (k=d, n=key)
            int nt0 = s0 >> 3;
            #pragma unroll
            for (int j = 0; j < 2; j++) {
                int kc = wn * 2 + j, ne = 2 * j, no = ne + 1;
                uint4 ue, uo;
                sp2(R.c[mt][ne][0], R.c[mt][ne][1], ue.x, ue.z);   // rows g -> even ntile
                sp2(R.c[mt][no][0], R.c[mt][no][1], ue.y, ue.w);
                sp2(R.c[mt][ne][2], R.c[mt][ne][3], uo.x, uo.z);   // rows g+8 -> odd ntile
                sp2(R.c[mt][no][2], R.c[mt][no][3], uo.y, uo.w);
                *(uint4*)(g_kf + ((size_t)(((bh * 512 + nt0) * 4) + kc) * 32 + lane) * 4) = ue;
                *(uint4*)(g_kf + ((size_t)(((bh * 512 + nt0 + 1) * 4) + kc) * 32 + lane) * 4) = uo;
            }
        } else {
            // V natural [bh][s][64]
            float* r0 = g_v + (((size_t)bh * S_LEN + s0 + g) << 6);
            float* r1 = g_v + (((size_t)bh * S_LEN + s0 + g + 8) << 6);
            #pragma unroll
            for (int nt = 0; nt < 4; nt++) {
                int lcol = wn * 32 + nt * 8 + 2 * t;
                *(float2*)(r0 + lcol) = make_float2(R.c[mt][nt][0], R.c[mt][nt][1]);
                *(float2*)(r1 + lcol) = make_float2(R.c[mt][nt][2], R.c[mt][nt][3]);
            }
        }
    }
}

__global__ __launch_bounds__(256) void out_gemm(
    const float* __restrict__ bo, float* __restrict__ out)
{
    GemmOut R;
    gemm_core(g_cf, g_wf + 3u * WFRAG, blockIdx.y * 8, blockIdx.x * 8, R);

    const int lane = threadIdx.x & 31, wid = threadIdx.x >> 5;
    const int wm = wid >> 1, wn = wid & 1;
    const int g = lane >> 2, t = lane & 3;
    const int col0 = blockIdx.x * 64;

    #pragma unroll
    for (int mt = 0; mt < 2; mt++) {
        int m0 = blockIdx.y * 128 + wm * 32 + mt * 16 + g;
        int m1 = m0 + 8;
        #pragma unroll
        for (int nt = 0; nt < 4; nt++) {
            int gcol = col0 + wn * 32 + nt * 8 + 2 * t;
            float bx = bo[gcol], by = bo[gcol + 1];
            *(float2*)(out + (size_t)m0 * DMODEL + gcol) =
                make_float2(R.c[mt][nt][0] + bx, R.c[mt][nt][1] + by);
            *(float2*)(out + (size_t)m1 * DMODEL + gcol) =
                make_float2(R.c[mt][nt][2] + bx, R.c[mt][nt][3] + by);
        }
    }
}

// ---------------------------------------------------------------------------
// Flash attention: 128 q-rows/CTA, 8 warps, 64-key tiles.
// bf16x3 QK and PV; P stays in registers (C-frag == A-frag for k16).
// smem: [buf0: K 4096 | V 4096][buf1: ...] u32 = 64KB dynamic.
// ---------------------------------------------------------------------------
__global__ __launch_bounds__(256) void flash_attn()
{
    extern __shared__ uint32_t sm[];
    const uint32_t smBase = (uint32_t)__cvta_generic_to_shared(sm);

    const int tid = threadIdx.x, lane = tid & 31, wid = tid >> 5;
    const int g = lane >> 2, t = lane & 3;
    const int qb = (gridDim.x - 1) - blockIdx.x;   // big blocks first
    const int bh = blockIdx.y;
    const int qrow0 = qb * 128 + wid * 16;

    // Q fragments (hi/lo) in registers
    uint4 qh[4], ql[4];
    {
        const int mq = bh * 256 + qb * 8 + wid;
        #pragma unroll
        for (int kc = 0; kc < 4; kc++) {
            size_t idx = ((size_t)(mq * 4 + kc) * 32 + lane) * 4;
            qh[kc] = *(const uint4*)(g_qf + idx);
            ql[kc] = *(const uint4*)(g_qf + AP2 + idx);
        }
    }

    float o[8][4];
    #pragma unroll
    for (int nt = 0; nt < 8; nt++)
        #pragma unroll
        for (int i = 0; i < 4; i++) o[nt][i] = 0.0f;
    float m_a = -1e30f, m_b = -1e30f, l_a = 0.0f, l_b = 0.0f;

    const int kt_end = 2 * qb + 1;

    // prologue: tile 0 -> buf 0 (K and V tiles are each 4096 u32, same offsets)
    {
        size_t base = (size_t)(bh * 2048) * 128;
        #pragma unroll
        for (int i = 0; i < 4; i++) {
            cpa16(smBase + (i * 1024 + tid * 4) * 4,        g_kf + base + i * 1024 + tid * 4);
            cpa16(smBase + (4096 + i * 1024 + tid * 4) * 4, g_vf + base + i * 1024 + tid * 4);
        }
        asm volatile("cp.async.commit_group;" ::: "memory");
    }

    for (int kt = 0; kt <= kt_end; kt++) {
        const int bufO = (kt & 1) * 8192;
        if (kt < kt_end) {
            const int nb = ((kt + 1) & 1) * 8192;
            size_t base = (size_t)(bh * 2048 + (kt + 1) * 32) * 128;
            #pragma unroll
            for (int i = 0; i < 4; i++) {
                cpa16(smBase + (nb + i * 1024 + tid * 4) * 4,        g_kf + base + i * 1024 + tid * 4);
                cpa16(smBase + (nb + 4096 + i * 1024 + tid * 4) * 4, g_vf + base + i * 1024 + tid * 4);
            }
            asm volatile("cp.async.commit_group;" ::: "memory");
            asm volatile("cp.async.wait_group 1;" ::: "memory");
        } else {
            asm volatile("cp.async.wait_group 0;" ::: "memory");
        }
        __syncthreads();

        const bool active = (kt * 64) <= (qrow0 + 15);
        if (active) {
            float s[8][4];
            #pragma unroll
            for (int nt = 0; nt < 8; nt++)
                #pragma unroll
                for (int i = 0; i < 4; i++) s[nt][i] = 0.0f;

            // S = Q K^T (bf16x3)
            #pragma unroll
            for (int kc = 0; kc < 4; kc++) {
                #pragma unroll
                for (int nt = 0; nt < 8; nt++) {
                    uint4 kb = *(const uint4*)&sm[bufO + ((nt * 4 + kc) * 32 + lane) * 4];
                    mma_bf16(s[nt], (const uint32_t*)&qh[kc], kb.x, kb.y);
                    mma_bf16(s[nt], (const uint32_t*)&qh[kc], kb.z, kb.w);
                    mma_bf16(s[nt], (const uint32_t*)&ql[kc], kb.x, kb.y);
                }
            }

            // causal mask
            if (kt * 64 + 63 > qrow0) {
                int ra = qrow0 + g, rb = ra + 8;
                #pragma unroll
                for (int nt = 0; nt < 8; nt++) {
                    int col = kt * 64 + nt * 8 + 2 * t;
                    if (col > ra)     s[nt][0] = -1e30f;
                    if (col + 1 > ra) s[nt][1] = -1e30f;
                    if (col > rb)     s[nt][2] = -1e30f;
                    if (col + 1 > rb) s[nt][3] = -1e30f;
                }
            }

            // online softmax (rows split across 4-lane groups)
            float mxa = -1e30f, mxb = -1e30f;
            #pragma unroll
            for (int nt = 0; nt < 8; nt++) {
                mxa = fmaxf(mxa, fmaxf(s[nt][0], s[nt][1]));
                mxb = fmaxf(mxb, fmaxf(s[nt][2], s[nt][3]));
            }
            mxa = fmaxf(mxa, __shfl_xor_sync(0xffffffffu, mxa, 1));
            mxa = fmaxf(mxa, __shfl_xor_sync(0xffffffffu, mxa, 2));
            mxb = fmaxf(mxb, __shfl_xor_sync(0xffffffffu, mxb, 1));
            mxb = fmaxf(mxb, __shfl_xor_sync(0xffffffffu, mxb, 2));

            float mna = fmaxf(m_a, mxa), mnb = fmaxf(m_b, mxb);
            float alpha_a = __expf(m_a - mna), alpha_b = __expf(m_b - mnb);
            m_a = mna; m_b = mnb;

            float sa = 0.0f, sb = 0.0f;
            #pragma unroll
            for (int nt = 0; nt < 8; nt++) {
                s[nt][0] = __expf(s[nt][0] - mna);
                s[nt][1] = __expf(s[nt][1] - mna);
                s[nt][2] = __expf(s[nt][2] - mnb);
                s[nt][3] = __expf(s[nt][3] - mnb);
                sa += s[nt][0] + s[nt][1];
                sb += s[nt][2] + s[nt][3];
            }
            sa += __shfl_xor_sync(0xffffffffu, sa, 1);
            sa += __shfl_xor_sync(0xffffffffu, sa, 2);
            sb += __shfl_xor_sync(0xffffffffu, sb, 1);
            sb += __shfl_xor_sync(0xffffffffu, sb, 2);
            l_a = l_a * alpha_a + sa;
            l_b = l_b * alpha_b + sb;

            #pragma unroll
            for (int nt = 0; nt < 8; nt++) {
                o[nt][0] *= alpha_a; o[nt][1] *= alpha_a;
                o[nt][2] *= alpha_b; o[nt][3] *= alpha_b;
            }

            // O += P V: P C-frag reinterpreted as A-frag (k16 identity), bf16x3
            #pragma unroll
            for (int ks2 = 0; ks2 < 4; ks2++) {
                int ne = 2 * ks2, no = ne + 1;
                uint32_t ph[4], pl[4];
                sp2(s[ne][0], s[ne][1], ph[0], pl[0]);
                sp2(s[ne][2], s[ne][3], ph[1], pl[1]);
                sp2(s[no][0], s[no][1], ph[2], pl[2]);
                sp2(s[no][2], s[no][3], ph[3], pl[3]);
                #pragma unroll
                for (int nt = 0; nt < 8; nt++) {
                    uint4 vb = *(const uint4*)&sm[bufO + 4096 + ((ks2 * 8 + nt) * 32 + lane) * 4];
                    mma_bf16(o[nt], ph, vb.x, vb.y);
                    mma_bf16(o[nt], ph, vb.z, vb.w);
                    mma_bf16(o[nt], pl, vb.x, vb.y);
                }
            }
        }
        __syncthreads();   // all reads of this buf done before its next overwrite
    }

    // normalize + store ctx as A-frags (C-frag == A-frag identity)
    const int b = bh / NH, hh = bh % NH;
    const float inva = 1.0f / l_a, invb = 1.0f / l_b;
    const int mtc = b * 256 + qb * 8 + wid;
    #pragma unroll
    for (int j = 0; j < 4; j++) {
        int ne = 2 * j, no = ne + 1;
        uint4 hc, lc;
        sp2(o[ne][0] * inva, o[ne][1] * inva, hc.x, lc.x);
        sp2(o[ne][2] * invb, o[ne][3] * invb, hc.y, lc.y);
        sp2(o[no][0] * inva, o[no][1] * inva, hc.z, lc.z);
        sp2(o[no][2] * invb, o[no][3] * invb, hc.w, lc.w);
        uint32_t* dst = g_cf + ((size_t)(mtc * 48 + hh * 4 + j) * 32 + lane) * 4;
        *(uint4*)dst = hc;
        *(uint4*)(dst + AP2) = lc;
    }
}

// ---------------------------------------------------------------------------

extern "C" void kernel_launch(void* const* d_in, const int* in_sizes, int n_in,
                              void* d_out, int out_size)
{
    const float* x  = (const float*)d_in[0];
    const float* Wq = (const float*)d_in[1];
    const float* Wk = (const float*)d_in[2];
    const float* Wv = (const float*)d_in[3];
    const float* Wo = (const float*)d_in[4];
    const float* bo = (const float*)d_in[5];
    float* out = (float*)d_out;

    cudaFuncSetAttribute(flash_attn, cudaFuncAttributeMaxDynamicSharedMemorySize, 65536);

    split_w_k<<<dim3(576, 4), 256>>>(Wq, Wk, Wv, Wo);
    split_x_k<<<3072, 256>>>(x);
    qkv_gemm<<<dim3(12, 64, 3), 256>>>();
    split_vb_k<<<6144, 256>>>();
    flash_attn<<<dim3(32, BH), 256, 65536>>>();
    out_gemm<<<dim3(12, 64), 256>>>(bo, out);
}

// round 10
// speedup vs baseline: 3.3411x; 1.0495x over previous
#include <cuda_runtime.h>
#include <cuda_bf16.h>
#include <cstdint>

#define S_LEN  4096
#define BATCH  2
#define NH     12
#define DH     64
#define DMODEL 768
#define MROWS  (BATCH * S_LEN)   // 8192
#define BH     (BATCH * NH)      // 24
#define AP2    3145728u          // u32 per A-frag plane

// ---------------------------------------------------------------------------
// Device scratch (allocation-free rule)
// ---------------------------------------------------------------------------
__device__ __align__(128) float    g_v [BH * S_LEN * DH];      // V natural (for split_vb)
__device__ __align__(128) uint32_t g_xf[2 * AP2];              // x   A-frags hi/lo (bf16x2)
__device__ __align__(128) uint32_t g_cf[2 * AP2];              // ctx A-frags hi/lo
__device__ __align__(128) uint32_t g_qf[2 * AP2];              // Q   A-frags hi/lo
__device__ __align__(128) uint32_t g_kf[6291456];              // K B-frags packed (bh0,bh1,bl0,bl1)
__device__ __align__(128) uint32_t g_vf[6291456];              // V B-frags packed
#define WFRAG 589824u
__device__ __align__(128) uint32_t g_wf[4 * WFRAG];            // Wq,Wk,Wv,Wo B-frags packed

// ---------------------------------------------------------------------------
// bf16 / mma helpers
// ---------------------------------------------------------------------------
__device__ __forceinline__ float bfhi(float x) {
    return __bfloat162float(__float2bfloat16(x));
}
__device__ __forceinline__ uint32_t packbf(float e0, float e1) {
    uint32_t r;
    asm("cvt.rn.bf16x2.f32 %0, %1, %2;" : "=r"(r) : "f"(e1), "f"(e0));
    return r;
}
__device__ __forceinline__ void mma_bf16(float* c, const uint32_t* a, uint32_t b0, uint32_t b1) {
    asm("mma.sync.aligned.m16n8k16.row.col.f32.bf16.bf16.f32 "
        "{%0,%1,%2,%3},{%4,%5,%6,%7},{%8,%9},{%0,%1,%2,%3};"
        : "+f"(c[0]), "+f"(c[1]), "+f"(c[2]), "+f"(c[3])
        : "r"(a[0]), "r"(a[1]), "r"(a[2]), "r"(a[3]), "r"(b0), "r"(b1));
}
__device__ __forceinline__ void cpa16(uint32_t saddr, const void* g) {
    asm volatile("cp.async.cg.shared.global [%0], [%1], 16;" :: "r"(saddr), "l"(g) : "memory");
}
__device__ __forceinline__ void sp2(float e0, float e1, uint32_t& h, uint32_t& l) {
    float h0 = bfhi(e0), h1 = bfhi(e1);
    h = packbf(h0, h1);
    l = packbf(e0 - h0, e1 - h1);
}

// Fragment layouts (m16n8k16, lane = g*4+t):
//  A: a0=(g,2t..2t+1) a1=(g+8,2t..) a2=(g,2t+8..) a3=(g+8,2t+8..)
//  B: b0=(k 2t..2t+1, n g)  b1=(k 2t+8..2t+9, n g)
//  C: c0=(g,2t) c1=(g,2t+1) c2=(g+8,2t) c3=(g+8,2t+1)

// ---------------------------------------------------------------------------
// Split kernels
// ---------------------------------------------------------------------------

// x -> A-frags: gs = mt*48 + kt2
__global__ __launch_bounds__(256) void split_x_k(const float* __restrict__ x) {
    int gtid = blockIdx.x * 256 + threadIdx.x;
    int lane = gtid & 31, gs = gtid >> 5;
    int g = lane >> 2, t = lane & 3;
    int mt = gs / 48, kt2 = gs % 48;
    const float* p = x + (size_t)(mt * 16 + g) * DMODEL + kt2 * 16 + 2 * t;
    float2 v00 = *(const float2*)p;
    float2 v10 = *(const float2*)(p + 8 * DMODEL);
    float2 v01 = *(const float2*)(p + 8);
    float2 v11 = *(const float2*)(p + 8 * DMODEL + 8);
    uint4 h, l;
    sp2(v00.x, v00.y, h.x, l.x);
    sp2(v10.x, v10.y, h.y, l.y);
    sp2(v01.x, v01.y, h.z, l.z);
    sp2(v11.x, v11.y, h.w, l.w);
    uint32_t* o = g_xf + (size_t)gs * 128 + lane * 4;
    *(uint4*)o = h;
    *(uint4*)(o + AP2) = l;
}

// weights [K=768][N=768] -> B-frags packed: gs = nt*48 + kt2
__global__ __launch_bounds__(256) void split_w_k(
    const float* __restrict__ w0, const float* __restrict__ w1,
    const float* __restrict__ w2, const float* __restrict__ w3)
{
    const float* src = (blockIdx.y == 0) ? w0 : (blockIdx.y == 1) ? w1
                     : (blockIdx.y == 2) ? w2 : w3;
    uint32_t* dst = g_wf + (size_t)blockIdx.y * WFRAG;
    int gtid = blockIdx.x * 256 + threadIdx.x;
    int lane = gtid & 31, gs = gtid >> 5;
    int g = lane >> 2, t = lane & 3;
    int nt = gs / 48, kt2 = gs % 48;
    int n = nt * 8 + g, k0 = kt2 * 16 + 2 * t;
    float v0 = src[(size_t)k0 * DMODEL + n];
    float v1 = src[(size_t)(k0 + 1) * DMODEL + n];
    float v2 = src[(size_t)(k0 + 8) * DMODEL + n];
    float v3 = src[(size_t)(k0 + 9) * DMODEL + n];
    uint4 u;
    sp2(v0, v1, u.x, u.z);
    sp2(v2, v3, u.y, u.w);
    *(uint4*)(dst + (size_t)gs * 128 + lane * 4) = u;
}

// V natural -> B-frags (k=key, n=d) packed: gs = (bh*256+ks2)*8 + ntd
__global__ __launch_bounds__(256) void split_vb_k() {
    int gtid = blockIdx.x * 256 + threadIdx.x;
    int lane = gtid & 31, gs = gtid >> 5;
    int g = lane >> 2, t = lane & 3;
    int ntd = gs & 7;
    int r = gs >> 3;
    int ks2 = r & 255, bh = r >> 8;
    int k0 = ks2 * 16 + 2 * t, d = ntd * 8 + g;
    const float* base = g_v + ((size_t)bh * S_LEN << 6);
    float v0 = base[((size_t)k0 << 6) + d];
    float v1 = base[((size_t)(k0 + 1) << 6) + d];
    float v2 = base[((size_t)(k0 + 8) << 6) + d];
    float v3 = base[((size_t)(k0 + 9) << 6) + d];
    uint4 u;
    sp2(v0, v1, u.x, u.z);
    sp2(v2, v3, u.y, u.w);
    *(uint4*)(g_vf + (size_t)gs * 128 + lane * 4) = u;
}

// ---------------------------------------------------------------------------
// GEMM core: 128x64 tile, BK=32 (2 k16 chunks/stage), 256 thr, double-buffered.
// ---------------------------------------------------------------------------
struct GemmOut { float c[2][4][4]; };

__device__ __forceinline__ void gemm_core(
    const uint32_t* __restrict__ af,   // A frags hi plane (lo at +AP2)
    const uint32_t* __restrict__ bf,   // B frags packed
    int mtBase, int ntBase, GemmOut& R)
{
    __shared__ uint32_t As[2][2][8][2][128];
    __shared__ uint32_t Bs[2][8][2][128];

    const int tid = threadIdx.x, lane = tid & 31, sub = tid >> 5;
    const int wm = sub >> 1, wn = sub & 1;

    #pragma unroll
    for (int mt = 0; mt < 2; mt++)
        #pragma unroll
        for (int nt = 0; nt < 4; nt++)
            #pragma unroll
            for (int i = 0; i < 4; i++) R.c[mt][nt][i] = 0.0f;

    uint4 pa[2][2], pb[2];
    #pragma unroll
    for (int ks = 0; ks < 2; ks++) {
        size_t ai = ((size_t)((mtBase + sub) * 48 + ks) * 32 + lane) * 4;
        pa[0][ks] = *(const uint4*)(af + ai);
        pa[1][ks] = *(const uint4*)(af + AP2 + ai);
        pb[ks] = *(const uint4*)(bf + ((size_t)((ntBase + sub) * 48 + ks) * 32 + lane) * 4);
    }
    #pragma unroll
    for (int ks = 0; ks < 2; ks++) {
        *(uint4*)&As[0][0][sub][ks][lane * 4] = pa[0][ks];
        *(uint4*)&As[0][1][sub][ks][lane * 4] = pa[1][ks];
        *(uint4*)&Bs[0][sub][ks][lane * 4]    = pb[ks];
    }
    __syncthreads();

    int buf = 0;
    for (int st = 1; st <= 24; st++) {
        if (st < 24) {
            #pragma unroll
            for (int ks = 0; ks < 2; ks++) {
                size_t ai = ((size_t)((mtBase + sub) * 48 + st * 2 + ks) * 32 + lane) * 4;
                pa[0][ks] = *(const uint4*)(af + ai);
                pa[1][ks] = *(const uint4*)(af + AP2 + ai);
                pb[ks] = *(const uint4*)(bf + ((size_t)((ntBase + sub) * 48 + st * 2 + ks) * 32 + lane) * 4);
            }
        }
        #pragma unroll
        for (int ks = 0; ks < 2; ks++) {
            uint4 a0h = *(const uint4*)&As[buf][0][wm * 2 + 0][ks][lane * 4];
            uint4 a1h = *(const uint4*)&As[buf][0][wm * 2 + 1][ks][lane * 4];
            uint4 a0l = *(const uint4*)&As[buf][1][wm * 2 + 0][ks][lane * 4];
            uint4 a1l = *(const uint4*)&As[buf][1][wm * 2 + 1][ks][lane * 4];
            #pragma unroll
            for (int nt = 0; nt < 4; nt++) {
                uint4 b = *(const uint4*)&Bs[buf][wn * 4 + nt][ks][lane * 4];
                mma_bf16(R.c[0][nt], (const uint32_t*)&a0h, b.x, b.y);
                mma_bf16(R.c[0][nt], (const uint32_t*)&a0h, b.z, b.w);
                mma_bf16(R.c[0][nt], (const uint32_t*)&a0l, b.x, b.y);
                mma_bf16(R.c[1][nt], (const uint32_t*)&a1h, b.x, b.y);
                mma_bf16(R.c[1][nt], (const uint32_t*)&a1h, b.z, b.w);
                mma_bf16(R.c[1][nt], (const uint32_t*)&a1l, b.x, b.y);
            }
        }
        if (st < 24) {
            #pragma unroll
            for (int ks = 0; ks < 2; ks++) {
                *(uint4*)&As[buf ^ 1][0][sub][ks][lane * 4] = pa[0][ks];
                *(uint4*)&As[buf ^ 1][1][sub][ks][lane * 4] = pa[1][ks];
                *(uint4*)&Bs[buf ^ 1][sub][ks][lane * 4]    = pb[ks];
            }
            __syncthreads();
            buf ^= 1;
        }
    }
}

// QKV GEMM. z=0: Q -> A-frags (scaled). z=1: K -> B-frags. z=2: V natural.
__global__ __launch_bounds__(256) void qkv_gemm() {
    const int z = blockIdx.z;
    const uint32_t* bfw = g_wf + (size_t)z * WFRAG;

    GemmOut R;
    gemm_core(g_xf, bfw, blockIdx.y * 8, blockIdx.x * 8, R);

    const int lane = threadIdx.x & 31, wid = threadIdx.x >> 5;
    const int wm = wid >> 1, wn = wid & 1;
    const int g = lane >> 2, t = lane & 3;
    const int h = blockIdx.x;            // one head per 64-col block

    #pragma unroll
    for (int mt = 0; mt < 2; mt++) {
        int m0 = blockIdx.y * 128 + wm * 32 + mt * 16;    // row-tile base (mult of 16)
        int b = m0 >> 12, s0 = m0 & 4095;
        int bh = b * NH + h;

        if (z == 0) {
            // Q A-frags, scale 1/8
            int mq = bh * 256 + (s0 >> 4);
            #pragma unroll
            for (int j = 0; j < 2; j++) {
                int ne = 2 * j, no = ne + 1;
                uint4 hq, lq;
                sp2(R.c[mt][ne][0] * 0.125f, R.c[mt][ne][1] * 0.125f, hq.x, lq.x);
                sp2(R.c[mt][ne][2] * 0.125f, R.c[mt][ne][3] * 0.125f, hq.y, lq.y);
                sp2(R.c[mt][no][0] * 0.125f, R.c[mt][no][1] * 0.125f, hq.z, lq.z);
                sp2(R.c[mt][no][2] * 0.125f, R.c[mt][no][3] * 0.125f, hq.w, lq.w);
                uint32_t* o = g_qf + ((size_t)(mq * 4 + wn * 2 + j) * 32 + lane) * 4;
                *(uint4*)o = hq;
                *(uint4*)(o + AP2) = lq;
            }
        } else if (z == 1) {
            // K B-frags: (k=d, n=key)
            int nt0 = s0 >> 3;
            #pragma unroll
            for (int j = 0; j < 2; j++) {
                int kc = wn * 2 + j, ne = 2 * j, no = ne + 1;
                uint4 ue, uo;
                sp2(R.c[mt][ne][0], R.c[mt][ne][1], ue.x, ue.z);
                sp2(R.c[mt][no][0], R.c[mt][no][1], ue.y, ue.w);
                sp2(R.c[mt][ne][2], R.c[mt][ne][3], uo.x, uo.z);
                sp2(R.c[mt][no][2], R.c[mt][no][3], uo.y, uo.w);
                *(uint4*)(g_kf + ((size_t)(((bh * 512 + nt0) * 4) + kc) * 32 + lane) * 4) = ue;
                *(uint4*)(g_kf + ((size_t)(((bh * 512 + nt0 + 1) * 4) + kc) * 32 + lane) * 4) = uo;
            }
        } else {
            // V natural [bh][s][64]
            float* r0 = g_v + (((size_t)bh * S_LEN + s0 + g) << 6);
            float* r1 = g_v + (((size_t)bh * S_LEN + s0 + g + 8) << 6);
            #pragma unroll
            for (int nt = 0; nt < 4; nt++) {
                int lcol = wn * 32 + nt * 8 + 2 * t;
                *(float2*)(r0 + lcol) = make_float2(R.c[mt][nt][0], R.c[mt][nt][1]);
                *(float2*)(r1 + lcol) = make_float2(R.c[mt][nt][2], R.c[mt][nt][3]);
            }
        }
    }
}

__global__ __launch_bounds__(256) void out_gemm(
    const float* __restrict__ bo, float* __restrict__ out)
{
    GemmOut R;
    gemm_core(g_cf, g_wf + 3u * WFRAG, blockIdx.y * 8, blockIdx.x * 8, R);

    const int lane = threadIdx.x & 31, wid = threadIdx.x >> 5;
    const int wm = wid >> 1, wn = wid & 1;
    const int g = lane >> 2, t = lane & 3;
    const int col0 = blockIdx.x * 64;

    #pragma unroll
    for (int mt = 0; mt < 2; mt++) {
        int m0 = blockIdx.y * 128 + wm * 32 + mt * 16 + g;
        int m1 = m0 + 8;
        #pragma unroll
        for (int nt = 0; nt < 4; nt++) {
            int gcol = col0 + wn * 32 + nt * 8 + 2 * t;
            float bx = bo[gcol], by = bo[gcol + 1];
            *(float2*)(out + (size_t)m0 * DMODEL + gcol) =
                make_float2(R.c[mt][nt][0] + bx, R.c[mt][nt][1] + by);
            *(float2*)(out + (size_t)m1 * DMODEL + gcol) =
                make_float2(R.c[mt][nt][2] + bx, R.c[mt][nt][3] + by);
        }
    }
}

// ---------------------------------------------------------------------------
// Flash attention: 128 q-rows/CTA, 8 warps, 64-key tiles.
// Q hi/lo fragments live in SMEM (cp.async'd once) to cut registers -> 2 CTA/SM.
// smem (u32): Q hi [0,4096) | Q lo [4096,8192) | buf0 K/V [8192,16384) |
//             buf1 K/V [16384,24576).  Total 96KB dynamic.
// ---------------------------------------------------------------------------
__global__ __launch_bounds__(256, 2) void flash_attn()
{
    extern __shared__ uint32_t sm[];
    const uint32_t smBase = (uint32_t)__cvta_generic_to_shared(sm);

    const int tid = threadIdx.x, lane = tid & 31, wid = tid >> 5;
    const int g = lane >> 2, t = lane & 3;
    const int qb = (gridDim.x - 1) - blockIdx.x;   // big blocks first
    const int bh = blockIdx.y;
    const int qrow0 = qb * 128 + wid * 16;

    float o[8][4];
    #pragma unroll
    for (int nt = 0; nt < 8; nt++)
        #pragma unroll
        for (int i = 0; i < 4; i++) o[nt][i] = 0.0f;
    float m_a = -1e30f, m_b = -1e30f, l_a = 0.0f, l_b = 0.0f;

    const int kt_end = 2 * qb + 1;

    // prologue group: Q frags (hi+lo, 8192 u32) + KV tile 0 -> buf 0
    {
        size_t qbase = (size_t)(bh * 256 + qb * 8) * 512;   // u32 offset of this CTA's Q frags
        #pragma unroll
        for (int i = 0; i < 4; i++) {
            cpa16(smBase + (i * 1024 + tid * 4) * 4,          g_qf + qbase + i * 1024 + tid * 4);
            cpa16(smBase + (4096 + i * 1024 + tid * 4) * 4,   g_qf + AP2 + qbase + i * 1024 + tid * 4);
        }
        size_t base = (size_t)(bh * 2048) * 128;
        #pragma unroll
        for (int i = 0; i < 4; i++) {
            cpa16(smBase + (8192 + i * 1024 + tid * 4) * 4,   g_kf + base + i * 1024 + tid * 4);
            cpa16(smBase + (12288 + i * 1024 + tid * 4) * 4,  g_vf + base + i * 1024 + tid * 4);
        }
        asm volatile("cp.async.commit_group;" ::: "memory");
    }

    for (int kt = 0; kt <= kt_end; kt++) {
        const int bufO = 8192 + (kt & 1) * 8192;
        if (kt < kt_end) {
            const int nb = 8192 + ((kt + 1) & 1) * 8192;
            size_t base = (size_t)(bh * 2048 + (kt + 1) * 32) * 128;
            #pragma unroll
            for (int i = 0; i < 4; i++) {
                cpa16(smBase + (nb + i * 1024 + tid * 4) * 4,        g_kf + base + i * 1024 + tid * 4);
                cpa16(smBase + (nb + 4096 + i * 1024 + tid * 4) * 4, g_vf + base + i * 1024 + tid * 4);
            }
            asm volatile("cp.async.commit_group;" ::: "memory");
            asm volatile("cp.async.wait_group 1;" ::: "memory");
        } else {
            asm volatile("cp.async.wait_group 0;" ::: "memory");
        }
        __syncthreads();

        const bool active = (kt * 64) <= (qrow0 + 15);
        if (active) {
            float s[8][4];
            #pragma unroll
            for (int nt = 0; nt < 8; nt++)
                #pragma unroll
                for (int i = 0; i < 4; i++) s[nt][i] = 0.0f;

            // S = Q K^T (bf16x3); Q frags streamed from smem per kc
            #pragma unroll
            for (int kc = 0; kc < 4; kc++) {
                uint4 qh = *(const uint4*)&sm[(wid * 4 + kc) * 128 + lane * 4];
                uint4 ql = *(const uint4*)&sm[4096 + (wid * 4 + kc) * 128 + lane * 4];
                #pragma unroll
                for (int nt = 0; nt < 8; nt++) {
                    uint4 kb = *(const uint4*)&sm[bufO + ((nt * 4 + kc) * 32 + lane) * 4];
                    mma_bf16(s[nt], (const uint32_t*)&qh, kb.x, kb.y);
                    mma_bf16(s[nt], (const uint32_t*)&qh, kb.z, kb.w);
                    mma_bf16(s[nt], (const uint32_t*)&ql, kb.x, kb.y);
                }
            }

            // causal mask
            if (kt * 64 + 63 > qrow0) {
                int ra = qrow0 + g, rb = ra + 8;
                #pragma unroll
                for (int nt = 0; nt < 8; nt++) {
                    int col = kt * 64 + nt * 8 + 2 * t;
                    if (col > ra)     s[nt][0] = -1e30f;
                    if (col + 1 > ra) s[nt][1] = -1e30f;
                    if (col > rb)     s[nt][2] = -1e30f;
                    if (col + 1 > rb) s[nt][3] = -1e30f;
                }
            }

            // online softmax (rows split across 4-lane groups)
            float mxa = -1e30f, mxb = -1e30f;
            #pragma unroll
            for (int nt = 0; nt < 8; nt++) {
                mxa = fmaxf(mxa, fmaxf(s[nt][0], s[nt][1]));
                mxb = fmaxf(mxb, fmaxf(s[nt][2], s[nt][3]));
            }
            mxa = fmaxf(mxa, __shfl_xor_sync(0xffffffffu, mxa, 1));
            mxa = fmaxf(mxa, __shfl_xor_sync(0xffffffffu, mxa, 2));
            mxb = fmaxf(mxb, __shfl_xor_sync(0xffffffffu, mxb, 1));
            mxb = fmaxf(mxb, __shfl_xor_sync(0xffffffffu, mxb, 2));

            float mna = fmaxf(m_a, mxa), mnb = fmaxf(m_b, mxb);
            float alpha_a = __expf(m_a - mna), alpha_b = __expf(m_b - mnb);
            m_a = mna; m_b = mnb;

            float sa = 0.0f, sb = 0.0f;
            #pragma unroll
            for (int nt = 0; nt < 8; nt++) {
                s[nt][0] = __expf(s[nt][0] - mna);
                s[nt][1] = __expf(s[nt][1] - mna);
                s[nt][2] = __expf(s[nt][2] - mnb);
                s[nt][3] = __expf(s[nt][3] - mnb);
                sa += s[nt][0] + s[nt][1];
                sb += s[nt][2] + s[nt][3];
            }
            sa += __shfl_xor_sync(0xffffffffu, sa, 1);
            sa += __shfl_xor_sync(0xffffffffu, sa, 2);
            sb += __shfl_xor_sync(0xffffffffu, sb, 1);
            sb += __shfl_xor_sync(0xffffffffu, sb, 2);
            l_a = l_a * alpha_a + sa;
            l_b = l_b * alpha_b + sb;

            #pragma unroll
            for (int nt = 0; nt < 8; nt++) {
                o[nt][0] *= alpha_a; o[nt][1] *= alpha_a;
                o[nt][2] *= alpha_b; o[nt][3] *= alpha_b;
            }

            // O += P V: P C-frag reinterpreted as A-frag (k16 identity), bf16x3
            #pragma unroll
            for (int ks2 = 0; ks2 < 4; ks2++) {
                int ne = 2 * ks2, no = ne + 1;
                uint32_t ph[4], pl[4];
                sp2(s[ne][0], s[ne][1], ph[0], pl[0]);
                sp2(s[ne][2], s[ne][3], ph[1], pl[1]);
                sp2(s[no][0], s[no][1], ph[2], pl[2]);
                sp2(s[no][2], s[no][3], ph[3], pl[3]);
                #pragma unroll
                for (int nt = 0; nt < 8; nt++) {
                    uint4 vb = *(const uint4*)&sm[bufO + 4096 + ((ks2 * 8 + nt) * 32 + lane) * 4];
                    mma_bf16(o[nt], ph, vb.x, vb.y);
                    mma_bf16(o[nt], ph, vb.z, vb.w);
                    mma_bf16(o[nt], pl, vb.x, vb.y);
                }
            }
        }
        __syncthreads();   // all reads of this buf done before its next overwrite
    }

    // normalize + store ctx as A-frags (C-frag == A-frag identity)
    const int b = bh / NH, hh = bh % NH;
    const float inva = 1.0f / l_a, invb = 1.0f / l_b;
    const int mtc = b * 256 + qb * 8 + wid;
    #pragma unroll
    for (int j = 0; j < 4; j++) {
        int ne = 2 * j, no = ne + 1;
        uint4 hc, lc;
        sp2(o[ne][0] * inva, o[ne][1] * inva, hc.x, lc.x);
        sp2(o[ne][2] * invb, o[ne][3] * invb, hc.y, lc.y);
        sp2(o[no][0] * inva, o[no][1] * inva, hc.z, lc.z);
        sp2(o[no][2] * invb, o[no][3] * invb, hc.w, lc.w);
        uint32_t* dst = g_cf + ((size_t)(mtc * 48 + hh * 4 + j) * 32 + lane) * 4;
        *(uint4*)dst = hc;
        *(uint4*)(dst + AP2) = lc;
    }
}

// ---------------------------------------------------------------------------

extern "C" void kernel_launch(void* const* d_in, const int* in_sizes, int n_in,
                              void* d_out, int out_size)
{
    const float* x  = (const float*)d_in[0];
    const float* Wq = (const float*)d_in[1];
    const float* Wk = (const float*)d_in[2];
    const float* Wv = (const float*)d_in[3];
    const float* Wo = (const float*)d_in[4];
    const float* bo = (const float*)d_in[5];
    float* out = (float*)d_out;

    cudaFuncSetAttribute(flash_attn, cudaFuncAttributeMaxDynamicSharedMemorySize, 98304);

    split_w_k<<<dim3(576, 4), 256>>>(Wq, Wk, Wv, Wo);
    split_x_k<<<3072, 256>>>(x);
    qkv_gemm<<<dim3(12, 64, 3), 256>>>();
    split_vb_k<<<6144, 256>>>();
    flash_attn<<<dim3(32, BH), 256, 98304>>>();
    out_gemm<<<dim3(12, 64), 256>>>(bo, out);
}

// round 15
// speedup vs baseline: 4.5869x; 1.3729x over previous
#include <cuda_runtime.h>
#include <cuda_fp16.h>
#include <cstdint>

#define S_LEN  4096
#define BATCH  2
#define NH     12
#define DH     64
#define DMODEL 768
#define MROWS  (BATCH * S_LEN)   // 8192
#define BH     (BATCH * NH)      // 24
#define AP2    3145728u          // u32 per A-frag plane

// ---------------------------------------------------------------------------
// Device scratch (allocation-free rule)
// ---------------------------------------------------------------------------
__device__ __align__(128) float    g_v [BH * S_LEN * DH];      // V natural (for split_vb)
__device__ __align__(128) uint32_t g_xf[2 * AP2];              // x   A-frags hi/lo (f16x2)
__device__ __align__(128) uint32_t g_cf[2 * AP2];              // ctx A-frags hi/lo
__device__ __align__(128) uint32_t g_qf[2 * AP2];              // Q   A-frags hi/lo
__device__ __align__(128) uint32_t g_kf[3145728];              // K B-frags single f16 (uint2/lane)
__device__ __align__(128) uint32_t g_vf[3145728];              // V B-frags single f16
#define WFRAG 294912u
__device__ __align__(128) uint32_t g_wf[4 * WFRAG];            // Wq,Wk,Wv,Wo B-frags single f16

// ---------------------------------------------------------------------------
// fp16 / mma helpers
// ---------------------------------------------------------------------------
__device__ __forceinline__ float f16hi(float x) {
    return __half2float(__float2half_rn(x));
}
// pack (k-even, k-odd) into one b32 (even in low half)
__device__ __forceinline__ uint32_t packh(float e0, float e1) {
    uint32_t r;
    asm("cvt.rn.f16x2.f32 %0, %1, %2;" : "=r"(r) : "f"(e1), "f"(e0));
    return r;
}
__device__ __forceinline__ void sp2h(float e0, float e1, uint32_t& h, uint32_t& l) {
    float h0 = f16hi(e0), h1 = f16hi(e1);
    h = packh(h0, h1);
    l = packh(e0 - h0, e1 - h1);
}
__device__ __forceinline__ void mma_f16(float* c, const uint32_t* a, uint32_t b0, uint32_t b1) {
    asm("mma.sync.aligned.m16n8k16.row.col.f32.f16.f16.f32 "
        "{%0,%1,%2,%3},{%4,%5,%6,%7},{%8,%9},{%0,%1,%2,%3};"
        : "+f"(c[0]), "+f"(c[1]), "+f"(c[2]), "+f"(c[3])
        : "r"(a[0]), "r"(a[1]), "r"(a[2]), "r"(a[3]), "r"(b0), "r"(b1));
}
__device__ __forceinline__ void cpa16(uint32_t saddr, const void* g) {
    asm volatile("cp.async.cg.shared.global [%0], [%1], 16;" :: "r"(saddr), "l"(g) : "memory");
}

// Fragment layouts (m16n8k16, lane = g*4+t):
//  A: a0=(g,2t..2t+1) a1=(g+8,2t..) a2=(g,2t+8..) a3=(g+8,2t+8..)
//  B: b0=(k 2t..2t+1, n g)  b1=(k 2t+8..2t+9, n g)
//  C: c0=(g,2t) c1=(g,2t+1) c2=(g+8,2t) c3=(g+8,2t+1)

// ---------------------------------------------------------------------------
// Split kernels
// ---------------------------------------------------------------------------

// x -> A-frags hi/lo: gs = mt*48 + kt2
__global__ __launch_bounds__(256) void split_x_k(const float* __restrict__ x) {
    int gtid = blockIdx.x * 256 + threadIdx.x;
    int lane = gtid & 31, gs = gtid >> 5;
    int g = lane >> 2, t = lane & 3;
    int mt = gs / 48, kt2 = gs % 48;
    const float* p = x + (size_t)(mt * 16 + g) * DMODEL + kt2 * 16 + 2 * t;
    float2 v00 = *(const float2*)p;
    float2 v10 = *(const float2*)(p + 8 * DMODEL);
    float2 v01 = *(const float2*)(p + 8);
    float2 v11 = *(const float2*)(p + 8 * DMODEL + 8);
    uint4 h, l;
    sp2h(v00.x, v00.y, h.x, l.x);
    sp2h(v10.x, v10.y, h.y, l.y);
    sp2h(v01.x, v01.y, h.z, l.z);
    sp2h(v11.x, v11.y, h.w, l.w);
    uint32_t* o = g_xf + (size_t)gs * 128 + lane * 4;
    *(uint4*)o = h;
    *(uint4*)(o + AP2) = l;
}

// weights [K=768][N=768] -> B-frags single f16: gs = nt*48 + kt2
__global__ __launch_bounds__(256) void split_w_k(
    const float* __restrict__ w0, const float* __restrict__ w1,
    const float* __restrict__ w2, const float* __restrict__ w3)
{
    const float* src = (blockIdx.y == 0) ? w0 : (blockIdx.y == 1) ? w1
                     : (blockIdx.y == 2) ? w2 : w3;
    uint32_t* dst = g_wf + (size_t)blockIdx.y * WFRAG;
    int gtid = blockIdx.x * 256 + threadIdx.x;
    int lane = gtid & 31, gs = gtid >> 5;
    int g = lane >> 2, t = lane & 3;
    int nt = gs / 48, kt2 = gs % 48;
    int n = nt * 8 + g, k0 = kt2 * 16 + 2 * t;
    float v0 = src[(size_t)k0 * DMODEL + n];
    float v1 = src[(size_t)(k0 + 1) * DMODEL + n];
    float v2 = src[(size_t)(k0 + 8) * DMODEL + n];
    float v3 = src[(size_t)(k0 + 9) * DMODEL + n];
    *(uint2*)(dst + (size_t)gs * 64 + lane * 2) = make_uint2(packh(v0, v1), packh(v2, v3));
}

// V natural -> B-frags single f16 (k=key, n=d): gs = (bh*256+ks2)*8 + ntd
__global__ __launch_bounds__(256) void split_vb_k() {
    int gtid = blockIdx.x * 256 + threadIdx.x;
    int lane = gtid & 31, gs = gtid >> 5;
    int g = lane >> 2, t = lane & 3;
    int ntd = gs & 7;
    int r = gs >> 3;
    int ks2 = r & 255, bh = r >> 8;
    int k0 = ks2 * 16 + 2 * t, d = ntd * 8 + g;
    const float* base = g_v + ((size_t)bh * S_LEN << 6);
    float v0 = base[((size_t)k0 << 6) + d];
    float v1 = base[((size_t)(k0 + 1) << 6) + d];
    float v2 = base[((size_t)(k0 + 8) << 6) + d];
    float v3 = base[((size_t)(k0 + 9) << 6) + d];
    *(uint2*)(g_vf + (size_t)gs * 64 + lane * 2) = make_uint2(packh(v0, v1), packh(v2, v3));
}

// ---------------------------------------------------------------------------
// GEMM core: 128x64 tile, BK=32 (2 k16 chunks/stage), 256 thr, double-buffered.
// A split hi/lo (2 passes), B single f16.
// ---------------------------------------------------------------------------
struct GemmOut { float c[2][4][4]; };

__device__ __forceinline__ void gemm_core(
    const uint32_t* __restrict__ af,   // A frags hi plane (lo at +AP2)
    const uint32_t* __restrict__ bf,   // B frags single
    int mtBase, int ntBase, GemmOut& R)
{
    __shared__ uint32_t As[2][2][8][2][128];
    __shared__ uint32_t Bs[2][8][2][64];

    const int tid = threadIdx.x, lane = tid & 31, sub = tid >> 5;
    const int wm = sub >> 1, wn = sub & 1;

    #pragma unroll
    for (int mt = 0; mt < 2; mt++)
        #pragma unroll
        for (int nt = 0; nt < 4; nt++)
            #pragma unroll
            for (int i = 0; i < 4; i++) R.c[mt][nt][i] = 0.0f;

    uint4 pa[2][2];
    uint2 pb[2];
    #pragma unroll
    for (int ks = 0; ks < 2; ks++) {
        size_t ai = ((size_t)((mtBase + sub) * 48 + ks) * 32 + lane) * 4;
        pa[0][ks] = *(const uint4*)(af + ai);
        pa[1][ks] = *(const uint4*)(af + AP2 + ai);
        pb[ks] = *(const uint2*)(bf + ((size_t)((ntBase + sub) * 48 + ks) * 32 + lane) * 2);
    }
    #pragma unroll
    for (int ks = 0; ks < 2; ks++) {
        *(uint4*)&As[0][0][sub][ks][lane * 4] = pa[0][ks];
        *(uint4*)&As[0][1][sub][ks][lane * 4] = pa[1][ks];
        *(uint2*)&Bs[0][sub][ks][lane * 2]    = pb[ks];
    }
    __syncthreads();

    int buf = 0;
    for (int st = 1; st <= 24; st++) {
        if (st < 24) {
            #pragma unroll
            for (int ks = 0; ks < 2; ks++) {
                size_t ai = ((size_t)((mtBase + sub) * 48 + st * 2 + ks) * 32 + lane) * 4;
                pa[0][ks] = *(const uint4*)(af + ai);
                pa[1][ks] = *(const uint4*)(af + AP2 + ai);
                pb[ks] = *(const uint2*)(bf + ((size_t)((ntBase + sub) * 48 + st * 2 + ks) * 32 + lane) * 2);
            }
        }
        #pragma unroll
        for (int ks = 0; ks < 2; ks++) {
            uint4 a0h = *(const uint4*)&As[buf][0][wm * 2 + 0][ks][lane * 4];
            uint4 a1h = *(const uint4*)&As[buf][0][wm * 2 + 1][ks][lane * 4];
            uint4 a0l = *(const uint4*)&As[buf][1][wm * 2 + 0][ks][lane * 4];
            uint4 a1l = *(const uint4*)&As[buf][1][wm * 2 + 1][ks][lane * 4];
            #pragma unroll
            for (int nt = 0; nt < 4; nt++) {
                uint2 b = *(const uint2*)&Bs[buf][wn * 4 + nt][ks][lane * 2];
                mma_f16(R.c[0][nt], (const uint32_t*)&a0h, b.x, b.y);
                mma_f16(R.c[0][nt], (const uint32_t*)&a0l, b.x, b.y);
                mma_f16(R.c[1][nt], (const uint32_t*)&a1h, b.x, b.y);
                mma_f16(R.c[1][nt], (const uint32_t*)&a1l, b.x, b.y);
            }
        }
        if (st < 24) {
            #pragma unroll
            for (int ks = 0; ks < 2; ks++) {
                *(uint4*)&As[buf ^ 1][0][sub][ks][lane * 4] = pa[0][ks];
                *(uint4*)&As[buf ^ 1][1][sub][ks][lane * 4] = pa[1][ks];
                *(uint2*)&Bs[buf ^ 1][sub][ks][lane * 2]    = pb[ks];
            }
            __syncthreads();
            buf ^= 1;
        }
    }
}

// QKV GEMM. z=0: Q -> A-frags hi/lo (scaled). z=1: K -> B-frags single. z=2: V natural.
__global__ __launch_bounds__(256) void qkv_gemm() {
    const int z = blockIdx.z;
    const uint32_t* bfw = g_wf + (size_t)z * WFRAG;

    GemmOut R;
    gemm_core(g_xf, bfw, blockIdx.y * 8, blockIdx.x * 8, R);

    const int lane = threadIdx.x & 31, wid = threadIdx.x >> 5;
    const int wm = wid >> 1, wn = wid & 1;
    const int g = lane >> 2, t = lane & 3;
    const int h = blockIdx.x;            // one head per 64-col block

    #pragma unroll
    for (int mt = 0; mt < 2; mt++) {
        int m0 = blockIdx.y * 128 + wm * 32 + mt * 16;    // row-tile base (mult of 16)
        int b = m0 >> 12, s0 = m0 & 4095;
        int bh = b * NH + h;

        if (z == 0) {
            // Q A-frags hi/lo, scale 1/8
            int mq = bh * 256 + (s0 >> 4);
            #pragma unroll
            for (int j = 0; j < 2; j++) {
                int ne = 2 * j, no = ne + 1;
                uint4 hq, lq;
                sp2h(R.c[mt][ne][0] * 0.125f, R.c[mt][ne][1] * 0.125f, hq.x, lq.x);
                sp2h(R.c[mt][ne][2] * 0.125f, R.c[mt][ne][3] * 0.125f, hq.y, lq.y);
                sp2h(R.c[mt][no][0] * 0.125f, R.c[mt][no][1] * 0.125f, hq.z, lq.z);
                sp2h(R.c[mt][no][2] * 0.125f, R.c[mt][no][3] * 0.125f, hq.w, lq.w);
                uint32_t* o = g_qf + ((size_t)(mq * 4 + wn * 2 + j) * 32 + lane) * 4;
                *(uint4*)o = hq;
                *(uint4*)(o + AP2) = lq;
            }
        } else if (z == 1) {
            // K B-frags single f16: (k=d, n=key)
            int nt0 = s0 >> 3;
            #pragma unroll
            for (int j = 0; j < 2; j++) {
                int kc = wn * 2 + j, ne = 2 * j, no = ne + 1;
                // rows g -> even ntile, rows g+8 -> odd ntile
                uint2 ue = make_uint2(packh(R.c[mt][ne][0], R.c[mt][ne][1]),
                                      packh(R.c[mt][no][0], R.c[mt][no][1]));
                uint2 uo = make_uint2(packh(R.c[mt][ne][2], R.c[mt][ne][3]),
                                      packh(R.c[mt][no][2], R.c[mt][no][3]));
                *(uint2*)(g_kf + ((size_t)(((bh * 512 + nt0) * 4) + kc) * 32 + lane) * 2) = ue;
                *(uint2*)(g_kf + ((size_t)(((bh * 512 + nt0 + 1) * 4) + kc) * 32 + lane) * 2) = uo;
            }
        } else {
            // V natural [bh][s][64]
            float* r0 = g_v + (((size_t)bh * S_LEN + s0 + g) << 6);
            float* r1 = g_v + (((size_t)bh * S_LEN + s0 + g + 8) << 6);
            #pragma unroll
            for (int nt = 0; nt < 4; nt++) {
                int lcol = wn * 32 + nt * 8 + 2 * t;
                *(float2*)(r0 + lcol) = make_float2(R.c[mt][nt][0], R.c[mt][nt][1]);
                *(float2*)(r1 + lcol) = make_float2(R.c[mt][nt][2], R.c[mt][nt][3]);
            }
        }
    }
}

__global__ __launch_bounds__(256) void out_gemm(
    const float* __restrict__ bo, float* __restrict__ out)
{
    GemmOut R;
    gemm_core(g_cf, g_wf + 3u * WFRAG, blockIdx.y * 8, blockIdx.x * 8, R);

    const int lane = threadIdx.x & 31, wid = threadIdx.x >> 5;
    const int wm = wid >> 1, wn = wid & 1;
    const int g = lane >> 2, t = lane & 3;
    const int col0 = blockIdx.x * 64;

    #pragma unroll
    for (int mt = 0; mt < 2; mt++) {
        int m0 = blockIdx.y * 128 + wm * 32 + mt * 16 + g;
        int m1 = m0 + 8;
        #pragma unroll
        for (int nt = 0; nt < 4; nt++) {
            int gcol = col0 + wn * 32 + nt * 8 + 2 * t;
            float bx = bo[gcol], by = bo[gcol + 1];
            *(float2*)(out + (size_t)m0 * DMODEL + gcol) =
                make_float2(R.c[mt][nt][0] + bx, R.c[mt][nt][1] + by);
            *(float2*)(out + (size_t)m1 * DMODEL + gcol) =
                make_float2(R.c[mt][nt][2] + bx, R.c[mt][nt][3] + by);
        }
    }
}

// ---------------------------------------------------------------------------
// Flash attention: 128 q-rows/CTA, 8 warps, 64-key tiles.
// Q hi/lo in SMEM; K/V single f16 tiles cp.async double-buffered.
// smem (u32): Q hi [0,4096) | Q lo [4096,8192) |
//             buf0 K [8192,10240) V [10240,12288) | buf1 [12288,16384). 64KB.
// ---------------------------------------------------------------------------
__global__ __launch_bounds__(256, 2) void flash_attn()
{
    extern __shared__ uint32_t sm[];
    const uint32_t smBase = (uint32_t)__cvta_generic_to_shared(sm);

    const int tid = threadIdx.x, lane = tid & 31, wid = tid >> 5;
    const int g = lane >> 2, t = lane & 3;
    const int qb = (gridDim.x - 1) - blockIdx.x;   // big blocks first
    const int bh = blockIdx.y;
    const int qrow0 = qb * 128 + wid * 16;

    float o[8][4];
    #pragma unroll
    for (int nt = 0; nt < 8; nt++)
        #pragma unroll
        for (int i = 0; i < 4; i++) o[nt][i] = 0.0f;
    float m_a = -1e30f, m_b = -1e30f, l_a = 0.0f, l_b = 0.0f;

    const int kt_end = 2 * qb + 1;

    // prologue group: Q frags (hi+lo, 8192 u32) + KV tile 0 -> buf 0
    {
        size_t qbase = (size_t)(bh * 256 + qb * 8) * 512;
        #pragma unroll
        for (int i = 0; i < 4; i++) {
            cpa16(smBase + (i * 1024 + tid * 4) * 4,        g_qf + qbase + i * 1024 + tid * 4);
            cpa16(smBase + (4096 + i * 1024 + tid * 4) * 4, g_qf + AP2 + qbase + i * 1024 + tid * 4);
        }
        size_t base = (size_t)(bh * 2048) * 64;
        #pragma unroll
        for (int i = 0; i < 2; i++) {
            cpa16(smBase + (8192 + i * 1024 + tid * 4) * 4,  g_kf + base + i * 1024 + tid * 4);
            cpa16(smBase + (10240 + i * 1024 + tid * 4) * 4, g_vf + base + i * 1024 + tid * 4);
        }
        asm volatile("cp.async.commit_group;" ::: "memory");
    }

    for (int kt = 0; kt <= kt_end; kt++) {
        const int bufO = 8192 + (kt & 1) * 4096;
        if (kt < kt_end) {
            const int nb = 8192 + ((kt + 1) & 1) * 4096;
            size_t base = (size_t)(bh * 2048 + (kt + 1) * 32) * 64;
            #pragma unroll
            for (int i = 0; i < 2; i++) {
                cpa16(smBase + (nb + i * 1024 + tid * 4) * 4,        g_kf + base + i * 1024 + tid * 4);
                cpa16(smBase + (nb + 2048 + i * 1024 + tid * 4) * 4, g_vf + base + i * 1024 + tid * 4);
            }
            asm volatile("cp.async.commit_group;" ::: "memory");
            asm volatile("cp.async.wait_group 1;" ::: "memory");
        } else {
            asm volatile("cp.async.wait_group 0;" ::: "memory");
        }
        __syncthreads();

        const bool active = (kt * 64) <= (qrow0 + 15);
        if (active) {
            float s[8][4];
            #pragma unroll
            for (int nt = 0; nt < 8; nt++)
                #pragma unroll
                for (int i = 0; i < 4; i++) s[nt][i] = 0.0f;

            // S = Q K^T (fp16x2: qh·k + ql·k)
            #pragma unroll
            for (int kc = 0; kc < 4; kc++) {
                uint4 qh = *(const uint4*)&sm[(wid * 4 + kc) * 128 + lane * 4];
                uint4 ql = *(const uint4*)&sm[4096 + (wid * 4 + kc) * 128 + lane * 4];
                #pragma unroll
                for (int nt = 0; nt < 8; nt++) {
                    uint2 kb = *(const uint2*)&sm[bufO + ((nt * 4 + kc) * 32 + lane) * 2];
                    mma_f16(s[nt], (const uint32_t*)&qh, kb.x, kb.y);
                    mma_f16(s[nt], (const uint32_t*)&ql, kb.x, kb.y);
                }
            }

            // causal mask
            if (kt * 64 + 63 > qrow0) {
                int ra = qrow0 + g, rb = ra + 8;
                #pragma unroll
                for (int nt = 0; nt < 8; nt++) {
                    int col = kt * 64 + nt * 8 + 2 * t;
                    if (col > ra)     s[nt][0] = -1e30f;
                    if (col + 1 > ra) s[nt][1] = -1e30f;
                    if (col > rb)     s[nt][2] = -1e30f;
                    if (col + 1 > rb) s[nt][3] = -1e30f;
                }
            }

            // online softmax (rows split across 4-lane groups)
            float mxa = -1e30f, mxb = -1e30f;
            #pragma unroll
            for (int nt = 0; nt < 8; nt++) {
                mxa = fmaxf(mxa, fmaxf(s[nt][0], s[nt][1]));
                mxb = fmaxf(mxb, fmaxf(s[nt][2], s[nt][3]));
            }
            mxa = fmaxf(mxa, __shfl_xor_sync(0xffffffffu, mxa, 1));
            mxa = fmaxf(mxa, __shfl_xor_sync(0xffffffffu, mxa, 2));
            mxb = fmaxf(mxb, __shfl_xor_sync(0xffffffffu, mxb, 1));
            mxb = fmaxf(mxb, __shfl_xor_sync(0xffffffffu, mxb, 2));

            float mna = fmaxf(m_a, mxa), mnb = fmaxf(m_b, mxb);
            float alpha_a = __expf(m_a - mna), alpha_b = __expf(m_b - mnb);
            m_a = mna; m_b = mnb;

            float sa = 0.0f, sb = 0.0f;
            #pragma unroll
            for (int nt = 0; nt < 8; nt++) {
                s[nt][0] = __expf(s[nt][0] - mna);
                s[nt][1] = __expf(s[nt][1] - mna);
                s[nt][2] = __expf(s[nt][2] - mnb);
                s[nt][3] = __expf(s[nt][3] - mnb);
                sa += s[nt][0] + s[nt][1];
                sb += s[nt][2] + s[nt][3];
            }
            sa += __shfl_xor_sync(0xffffffffu, sa, 1);
            sa += __shfl_xor_sync(0xffffffffu, sa, 2);
            sb += __shfl_xor_sync(0xffffffffu, sb, 1);
            sb += __shfl_xor_sync(0xffffffffu, sb, 2);
            l_a = l_a * alpha_a + sa;
            l_b = l_b * alpha_b + sb;

            #pragma unroll
            for (int nt = 0; nt < 8; nt++) {
                o[nt][0] *= alpha_a; o[nt][1] *= alpha_a;
                o[nt][2] *= alpha_b; o[nt][3] *= alpha_b;
            }

            // O += P V: P C-frag == A-frag (k16 identity); P split f16, V single
            #pragma unroll
            for (int ks2 = 0; ks2 < 4; ks2++) {
                int ne = 2 * ks2, no = ne + 1;
                uint32_t ph[4], pl[4];
                sp2h(s[ne][0], s[ne][1], ph[0], pl[0]);
                sp2h(s[ne][2], s[ne][3], ph[1], pl[1]);
                sp2h(s[no][0], s[no][1], ph[2], pl[2]);
                sp2h(s[no][2], s[no][3], ph[3], pl[3]);
                #pragma unroll
                for (int nt = 0; nt < 8; nt++) {
                    uint2 vb = *(const uint2*)&sm[bufO + 2048 + ((ks2 * 8 + nt) * 32 + lane) * 2];
                    mma_f16(o[nt], ph, vb.x, vb.y);
                    mma_f16(o[nt], pl, vb.x, vb.y);
                }
            }
        }
        __syncthreads();   // all reads of this buf done before its next overwrite
    }

    // normalize + store ctx as A-frags hi/lo (C-frag == A-frag identity)
    const int b = bh / NH, hh = bh % NH;
    const float inva = 1.0f / l_a, invb = 1.0f / l_b;
    const int mtc = b * 256 + qb * 8 + wid;
    #pragma unroll
    for (int j = 0; j < 4; j++) {
        int ne = 2 * j, no = ne + 1;
        uint4 hc, lc;
        sp2h(o[ne][0] * inva, o[ne][1] * inva, hc.x, lc.x);
        sp2h(o[ne][2] * invb, o[ne][3] * invb, hc.y, lc.y);
        sp2h(o[no][0] * inva, o[no][1] * inva, hc.z, lc.z);
        sp2h(o[no][2] * invb, o[no][3] * invb, hc.w, lc.w);
        uint32_t* dst = g_cf + ((size_t)(mtc * 48 + hh * 4 + j) * 32 + lane) * 4;
        *(uint4*)dst = hc;
        *(uint4*)(dst + AP2) = lc;
    }
}

// ---------------------------------------------------------------------------

extern "C" void kernel_launch(void* const* d_in, const int* in_sizes, int n_in,
                              void* d_out, int out_size)
{
    const float* x  = (const float*)d_in[0];
    const float* Wq = (const float*)d_in[1];
    const float* Wk = (const float*)d_in[2];
    const float* Wv = (const float*)d_in[3];
    const float* Wo = (const float*)d_in[4];
    const float* bo = (const float*)d_in[5];
    float* out = (float*)d_out;

    cudaFuncSetAttribute(flash_attn, cudaFuncAttributeMaxDynamicSharedMemorySize, 65536);

    split_w_k<<<dim3(576, 4), 256>>>(Wq, Wk, Wv, Wo);
    split_x_k<<<3072, 256>>>(x);
    qkv_gemm<<<dim3(12, 64, 3), 256>>>();
    split_vb_k<<<6144, 256>>>();
    flash_attn<<<dim3(32, BH), 256, 65536>>>();
    out_gemm<<<dim3(12, 64), 256>>>(bo, out);
}